// round 1
// baseline (speedup 1.0000x reference)
#include <cuda_runtime.h>
#include <cuda_bf16.h>
#include <math.h>

// Problem shape (fixed)
#define Bp 4
#define Tp 2048
#define Cp 2048
#define Hp 16
#define Dp 128
#define BHp (Bp*Hp)        // 64
#define BTp (Bp*Tp)        // 8192
#define SCALE 0.08838834764831845f  // 1/sqrt(128)

// Scratch (device globals; allocation-free per harness rules)
__device__ float g_q [BHp * Tp * Dp];   // [B,H,T,d]
__device__ float g_k [BHp * Tp * Dp];
__device__ float g_v [BHp * Tp * Dp];
__device__ float g_ao[BTp * Cp];        // attention out, [B,T,C]

// ---------------------------------------------------------------------------
// GEMM: C[m][n] = sum_k A[m][k] * B[n][k]   (both operands K-major / "NT")
// BM=BN=128, BK=16, 256 threads, 8x8 micro-tile per thread.
// EPI=0: plain store to Cq (MxN row-major)
// EPI=1: scatter qkv -> g_q/g_k/g_v in [B,H,T,d] layout
// ---------------------------------------------------------------------------
#define BM 128
#define BN 128
#define BK 16

template <int EPI>
__global__ void __launch_bounds__(256)
gemm_nt(const float* __restrict__ A, const float* __restrict__ B,
        float* __restrict__ Cq, float* __restrict__ Ck, float* __restrict__ Cv,
        int M, int N, int K)
{
    __shared__ float As[BK][BM + 4];
    __shared__ float Bs[BK][BN + 4];

    const int tid = threadIdx.x;
    const int m0 = blockIdx.y * BM;
    const int n0 = blockIdx.x * BN;
    const int ty = tid >> 4;        // 0..15
    const int tx = tid & 15;        // 0..15

    const int lrow = tid >> 1;          // 0..127
    const int lcol = (tid & 1) * 8;     // 0 or 8

    float acc[8][8];
#pragma unroll
    for (int i = 0; i < 8; i++)
#pragma unroll
        for (int j = 0; j < 8; j++) acc[i][j] = 0.f;

    const float* Ap = A + (long)(m0 + lrow) * K + lcol;
    const float* Bp_ = B + (long)(n0 + lrow) * K + lcol;

    for (int kt = 0; kt < K; kt += BK) {
        float4 a0 = *(const float4*)(Ap + kt);
        float4 a1 = *(const float4*)(Ap + kt + 4);
        float4 b0 = *(const float4*)(Bp_ + kt);
        float4 b1 = *(const float4*)(Bp_ + kt + 4);
        __syncthreads();
        As[lcol + 0][lrow] = a0.x; As[lcol + 1][lrow] = a0.y;
        As[lcol + 2][lrow] = a0.z; As[lcol + 3][lrow] = a0.w;
        As[lcol + 4][lrow] = a1.x; As[lcol + 5][lrow] = a1.y;
        As[lcol + 6][lrow] = a1.z; As[lcol + 7][lrow] = a1.w;
        Bs[lcol + 0][lrow] = b0.x; Bs[lcol + 1][lrow] = b0.y;
        Bs[lcol + 2][lrow] = b0.z; Bs[lcol + 3][lrow] = b0.w;
        Bs[lcol + 4][lrow] = b1.x; Bs[lcol + 5][lrow] = b1.y;
        Bs[lcol + 6][lrow] = b1.z; Bs[lcol + 7][lrow] = b1.w;
        __syncthreads();
#pragma unroll
        for (int k = 0; k < BK; k++) {
            float a[8], b[8];
            *(float4*)&a[0] = *(const float4*)&As[k][ty * 8];
            *(float4*)&a[4] = *(const float4*)&As[k][ty * 8 + 4];
            *(float4*)&b[0] = *(const float4*)&Bs[k][tx * 8];
            *(float4*)&b[4] = *(const float4*)&Bs[k][tx * 8 + 4];
#pragma unroll
            for (int i = 0; i < 8; i++)
#pragma unroll
                for (int j = 0; j < 8; j++) acc[i][j] += a[i] * b[j];
        }
    }

    if (EPI == 0) {
#pragma unroll
        for (int i = 0; i < 8; i++) {
            long row = m0 + ty * 8 + i;
            float* dst = Cq + row * N + n0 + tx * 8;
            float4 v0, v1;
            v0.x = acc[i][0]; v0.y = acc[i][1]; v0.z = acc[i][2]; v0.w = acc[i][3];
            v1.x = acc[i][4]; v1.y = acc[i][5]; v1.z = acc[i][6]; v1.w = acc[i][7];
            *(float4*)dst = v0; *(float4*)(dst + 4) = v1;
        }
    } else {
        const int n = n0 + tx * 8;
        const int which = n >> 11;           // 0=q,1=k,2=v  (C=2048)
        const int rem = n & 2047;
        const int h = rem >> 7;
        const int dd = rem & 127;
        float* base = (which == 0) ? Cq : (which == 1) ? Ck : Cv;
#pragma unroll
        for (int i = 0; i < 8; i++) {
            int m = m0 + ty * 8 + i;
            int b = m >> 11;                 // T=2048
            int t = m & 2047;
            float* dst = base + (((long)(b * Hp + h) * Tp + t) * Dp + dd);
            float4 v0, v1;
            v0.x = acc[i][0]; v0.y = acc[i][1]; v0.z = acc[i][2]; v0.w = acc[i][3];
            v1.x = acc[i][4]; v1.y = acc[i][5]; v1.z = acc[i][6]; v1.w = acc[i][7];
            *(float4*)dst = v0; *(float4*)(dst + 4) = v1;
        }
    }
}

// ---------------------------------------------------------------------------
// Causal flash attention, fp32, online softmax.
// grid = (T/64, B*H), 256 threads.
// Q tile [64][128] resident; loop over K/V tiles [64][128] (causal skip).
// S compute mapping: 4x4 micro-tile per thread (16x16 thread grid).
// Softmax/O mapping: 4 threads per query row, 32 d-dims each.
// ---------------------------------------------------------------------------
#define QPAD 132
#define SPAD 68
#define ATTN_SMEM ((64*QPAD + 64*QPAD + 64*128 + 64*SPAD) * 4)

__global__ void __launch_bounds__(256)
attn_kernel(const float* __restrict__ Q, const float* __restrict__ Kg,
            const float* __restrict__ Vg, float* __restrict__ O)
{
    extern __shared__ float sm[];
    float* Qs = sm;                    // [64][132]
    float* Ks = Qs + 64 * QPAD;        // [64][132]
    float* Vs = Ks + 64 * QPAD;        // [64][128]
    float* Ss = Vs + 64 * 128;         // [64][68]

    const int tid = threadIdx.x;
    const int qt = blockIdx.x;         // 0..31
    const int bh = blockIdx.y;         // 0..63
    const int q0 = qt * 64;
    const long base = (long)bh * Tp * Dp;

    for (int i = tid; i < 64 * 128; i += 256)
        Qs[(i >> 7) * QPAD + (i & 127)] = Q[base + (long)q0 * Dp + i];

    const int r  = tid >> 2;           // query row 0..63
    const int d0 = (tid & 3) * 32;     // d segment
    const int sr = (tid >> 4) * 4;     // S rows
    const int sc = (tid & 15) * 4;     // S cols

    float acc[32];
#pragma unroll
    for (int i = 0; i < 32; i++) acc[i] = 0.f;
    float m_i = -1e30f, l_i = 0.f;

    for (int j = 0; j <= qt; j++) {
        __syncthreads();
        for (int i = tid; i < 64 * 128; i += 256) {
            int rr = i >> 7, cc = i & 127;
            float kv = Kg[base + (long)j * 64 * Dp + i];
            float vv = Vg[base + (long)j * 64 * Dp + i];
            Ks[rr * QPAD + cc] = kv;
            Vs[rr * 128 + cc] = vv;
        }
        __syncthreads();

        // S[64][64] = Qs * Ks^T
        float s[4][4];
#pragma unroll
        for (int a = 0; a < 4; a++)
#pragma unroll
            for (int b = 0; b < 4; b++) s[a][b] = 0.f;

        for (int k = 0; k < 128; k += 4) {
            float4 q4[4], k4[4];
#pragma unroll
            for (int a = 0; a < 4; a++) q4[a] = *(const float4*)&Qs[(sr + a) * QPAD + k];
#pragma unroll
            for (int b = 0; b < 4; b++) k4[b] = *(const float4*)&Ks[(sc + b) * QPAD + k];
#pragma unroll
            for (int a = 0; a < 4; a++)
#pragma unroll
                for (int b = 0; b < 4; b++) {
                    s[a][b] += q4[a].x * k4[b].x;
                    s[a][b] += q4[a].y * k4[b].y;
                    s[a][b] += q4[a].z * k4[b].z;
                    s[a][b] += q4[a].w * k4[b].w;
                }
        }
#pragma unroll
        for (int a = 0; a < 4; a++) {
            float4 v;
            v.x = s[a][0] * SCALE; v.y = s[a][1] * SCALE;
            v.z = s[a][2] * SCALE; v.w = s[a][3] * SCALE;
            *(float4*)&Ss[(sr + a) * SPAD + sc] = v;
        }
        __syncthreads();

        // online softmax + O accumulate (4 threads per row, redundant m/l)
        const int climit = (j == qt) ? (r + 1) : 64;
        float mx = m_i;
        for (int c = 0; c < climit; c++) mx = fmaxf(mx, Ss[r * SPAD + c]);
        float corr = __expf(m_i - mx);
        m_i = mx;
        l_i *= corr;
#pragma unroll
        for (int i = 0; i < 32; i++) acc[i] *= corr;
        for (int c = 0; c < climit; c++) {
            float pv = __expf(Ss[r * SPAD + c] - mx);
            l_i += pv;
            const float* vrow = &Vs[c * 128 + d0];
#pragma unroll
            for (int i = 0; i < 8; i++) {
                float4 v4 = *(const float4*)&vrow[i * 4];
                acc[i * 4 + 0] += pv * v4.x;
                acc[i * 4 + 1] += pv * v4.y;
                acc[i * 4 + 2] += pv * v4.z;
                acc[i * 4 + 3] += pv * v4.w;
            }
        }
    }

    const float inv = 1.f / l_i;
    const int b = bh >> 4, h = bh & 15;
    const int t = q0 + r;
    float* op = O + ((long)(b * Tp + t) * Cp + h * Dp + d0);
#pragma unroll
    for (int i = 0; i < 8; i++) {
        float4 v4;
        v4.x = acc[i * 4 + 0] * inv; v4.y = acc[i * 4 + 1] * inv;
        v4.z = acc[i * 4 + 2] * inv; v4.w = acc[i * 4 + 3] * inv;
        *(float4*)&op[i * 4] = v4;
    }
}

// ---------------------------------------------------------------------------
extern "C" void kernel_launch(void* const* d_in, const int* in_sizes, int n_in,
                              void* d_out, int out_size)
{
    const float* x      = (const float*)d_in[0];  // [B,T,C]
    const float* W_attn = (const float*)d_in[1];  // [3C,C]
    const float* W_proj = (const float*)d_in[2];  // [C,C]
    float* out = (float*)d_out;                   // [B,T,C]

    float *pq, *pk, *pv, *pao;
    cudaGetSymbolAddress((void**)&pq,  g_q);
    cudaGetSymbolAddress((void**)&pk,  g_k);
    cudaGetSymbolAddress((void**)&pv,  g_v);
    cudaGetSymbolAddress((void**)&pao, g_ao);

    cudaFuncSetAttribute(attn_kernel,
                         cudaFuncAttributeMaxDynamicSharedMemorySize, ATTN_SMEM);

    // 1) QKV projection with scatter into [B,H,T,d]
    {
        dim3 grid(3 * Cp / BN, BTp / BM);
        gemm_nt<1><<<grid, 256>>>(x, W_attn, pq, pk, pv, BTp, 3 * Cp, Cp);
    }
    // 2) causal flash attention -> g_ao [B,T,C]
    {
        dim3 grid(Tp / 64, BHp);
        attn_kernel<<<grid, 256, ATTN_SMEM>>>(pq, pk, pv, pao);
    }
    // 3) output projection
    {
        dim3 grid(Cp / BN, BTp / BM);
        gemm_nt<0><<<grid, 256>>>(pao, W_proj, out, nullptr, nullptr, BTp, Cp, Cp);
    }
}

// round 5
// speedup vs baseline: 1.2989x; 1.2989x over previous
#include <cuda_runtime.h>
#include <cuda_bf16.h>
#include <cstdint>
#include <math.h>

// Problem shape (fixed)
#define Bp 4
#define Tp 2048
#define Cp 2048
#define Hp 16
#define Dp 128
#define BHp (Bp*Hp)        // 64
#define BTp (Bp*Tp)        // 8192
#define SCALE 0.08838834764831845f  // 1/sqrt(128)

// Scratch (device globals; allocation-free per harness rules)
__device__ float g_q [BHp * Tp * Dp];   // [B,H,T,d]
__device__ float g_k [BHp * Tp * Dp];
__device__ float g_v [BHp * Tp * Dp];
__device__ float g_ao[BTp * Cp];        // attention out, [B,T,C]

__device__ __forceinline__ uint32_t f2tf32(float x) {
    uint32_t r;
    asm("cvt.rna.tf32.f32 %0, %1;" : "=r"(r) : "f"(x));
    return r;
}

__device__ __forceinline__ void mma_tf32(float* d, const uint32_t* a, const uint32_t* b) {
    asm volatile(
        "mma.sync.aligned.m16n8k8.row.col.f32.tf32.tf32.f32 "
        "{%0,%1,%2,%3}, {%4,%5,%6,%7}, {%8,%9}, {%0,%1,%2,%3};"
        : "+f"(d[0]), "+f"(d[1]), "+f"(d[2]), "+f"(d[3])
        : "r"(a[0]), "r"(a[1]), "r"(a[2]), "r"(a[3]), "r"(b[0]), "r"(b[1]));
}

// ===========================================================================
// tf32 mma.sync GEMM:  C[m][n] = sum_k A[m][k]*B[n][k]   (NT, both K-major)
// BM=128, BN=128, BK=16, 256 threads (8 warps, 2x4), warp tile 64x32.
// Double-buffered smem, tf32 conversion on the STS path.
// EPI=0: row-major store. EPI=1: qkv scatter to [B,H,T,d].
// ===========================================================================
#define BM 128
#define BN 128
#define BK 16
#define KP 20   // BK + 4 pad -> conflict-free fragment LDS

template <int EPI>
__global__ void __launch_bounds__(256)
gemm_mma(const float* __restrict__ A, const float* __restrict__ B,
         float* __restrict__ Cq, float* __restrict__ Ck, float* __restrict__ Cv,
         int M, int N, int K)
{
    __shared__ uint32_t As[2][BM][KP];
    __shared__ uint32_t Bs[2][BN][KP];

    const int tid = threadIdx.x;
    const int lane = tid & 31;
    const int wid = tid >> 5;
    const int wm = (wid & 1) * 64;       // warp m offset
    const int wn = (wid >> 1) * 32;      // warp n offset
    const int m0 = blockIdx.y * BM;
    const int n0 = blockIdx.x * BN;

    const int ldrow = tid >> 2;          // 0..63 (x4 over i) -> rows 0..127 via cid
    const int ldc4  = tid & 3;           // float4 index within row

    float acc[4][4][4];
#pragma unroll
    for (int i = 0; i < 4; i++)
#pragma unroll
        for (int j = 0; j < 4; j++)
#pragma unroll
            for (int q = 0; q < 4; q++) acc[i][j][q] = 0.f;

    const int NK = K / BK;

    float4 ra[2], rb[2];
    // prologue: tile 0
#pragma unroll
    for (int i = 0; i < 2; i++) {
        int cid = tid + 256 * i; int r = cid >> 2, c4 = cid & 3;
        ra[i] = *(const float4*)(A + (long)(m0 + r) * K + c4 * 4);
        rb[i] = *(const float4*)(B + (long)(n0 + r) * K + c4 * 4);
    }
#pragma unroll
    for (int i = 0; i < 2; i++) {
        int cid = tid + 256 * i; int r = cid >> 2, c4 = cid & 3;
        uint4 ua, ub;
        ua.x = f2tf32(ra[i].x); ua.y = f2tf32(ra[i].y);
        ua.z = f2tf32(ra[i].z); ua.w = f2tf32(ra[i].w);
        ub.x = f2tf32(rb[i].x); ub.y = f2tf32(rb[i].y);
        ub.z = f2tf32(rb[i].z); ub.w = f2tf32(rb[i].w);
        *(uint4*)&As[0][r][c4 * 4] = ua;
        *(uint4*)&Bs[0][r][c4 * 4] = ub;
    }
    __syncthreads();

    const int ar = lane >> 2;   // 0..7
    const int ac = lane & 3;    // 0..3

    for (int kt = 0; kt < NK; kt++) {
        const int s = kt & 1;
        const bool havenext = (kt + 1 < NK);
        if (havenext) {
            const int ko = (kt + 1) * BK;
#pragma unroll
            for (int i = 0; i < 2; i++) {
                int cid = tid + 256 * i; int r = cid >> 2, c4 = cid & 3;
                ra[i] = *(const float4*)(A + (long)(m0 + r) * K + ko + c4 * 4);
                rb[i] = *(const float4*)(B + (long)(n0 + r) * K + ko + c4 * 4);
            }
        }

#pragma unroll
        for (int ks = 0; ks < 2; ks++) {
            const int kc = ks * 8;
            uint32_t af[4][4], bf[4][2];
#pragma unroll
            for (int i = 0; i < 4; i++) {
                const int rb_ = wm + i * 16;
                af[i][0] = As[s][rb_ + ar][kc + ac];
                af[i][1] = As[s][rb_ + ar + 8][kc + ac];
                af[i][2] = As[s][rb_ + ar][kc + ac + 4];
                af[i][3] = As[s][rb_ + ar + 8][kc + ac + 4];
            }
#pragma unroll
            for (int j = 0; j < 4; j++) {
                const int cb = wn + j * 8;
                bf[j][0] = Bs[s][cb + ar][kc + ac];
                bf[j][1] = Bs[s][cb + ar][kc + ac + 4];
            }
#pragma unroll
            for (int i = 0; i < 4; i++)
#pragma unroll
                for (int j = 0; j < 4; j++)
                    mma_tf32(acc[i][j], af[i], bf[j]);
        }

        if (havenext) {
            __syncthreads();
            const int z = s ^ 1;
#pragma unroll
            for (int i = 0; i < 2; i++) {
                int cid = tid + 256 * i; int r = cid >> 2, c4 = cid & 3;
                uint4 ua, ub;
                ua.x = f2tf32(ra[i].x); ua.y = f2tf32(ra[i].y);
                ua.z = f2tf32(ra[i].z); ua.w = f2tf32(ra[i].w);
                ub.x = f2tf32(rb[i].x); ub.y = f2tf32(rb[i].y);
                ub.z = f2tf32(rb[i].z); ub.w = f2tf32(rb[i].w);
                *(uint4*)&As[z][r][c4 * 4] = ua;
                *(uint4*)&Bs[z][r][c4 * 4] = ub;
            }
            __syncthreads();
        }
    }

    // Epilogue: c0,c1 at (row=ar, col=2*ac), c2,c3 at (row=ar+8, col=2*ac)
#pragma unroll
    for (int i = 0; i < 4; i++) {
        const int mrow0 = m0 + wm + i * 16 + ar;
#pragma unroll
        for (int j = 0; j < 4; j++) {
            const int n = n0 + wn + j * 8 + ac * 2;
            if (EPI == 0) {
                float* d0 = Cq + (long)mrow0 * N + n;
                float* d1 = Cq + (long)(mrow0 + 8) * N + n;
                *(float2*)d0 = make_float2(acc[i][j][0], acc[i][j][1]);
                *(float2*)d1 = make_float2(acc[i][j][2], acc[i][j][3]);
            } else {
                const int which = n >> 11;
                const int rem = n & 2047;
                const int h = rem >> 7, dd = rem & 127;
                float* base = (which == 0) ? Cq : (which == 1) ? Ck : Cv;
                const int b0_ = mrow0 >> 11, t0 = mrow0 & 2047;
                const int b1_ = (mrow0 + 8) >> 11, t1 = (mrow0 + 8) & 2047;
                float* d0 = base + (((long)(b0_ * Hp + h) * Tp + t0) * Dp + dd);
                float* d1 = base + (((long)(b1_ * Hp + h) * Tp + t1) * Dp + dd);
                *(float2*)d0 = make_float2(acc[i][j][0], acc[i][j][1]);
                *(float2*)d1 = make_float2(acc[i][j][2], acc[i][j][3]);
            }
        }
    }
}

// ---------------------------------------------------------------------------
// Causal flash attention, fp32, online softmax (unchanged; R1-proven).
// ---------------------------------------------------------------------------
#define QPAD 132
#define SPAD 68
#define ATTN_SMEM ((64*QPAD + 64*QPAD + 64*128 + 64*SPAD) * 4)

__global__ void __launch_bounds__(256)
attn_kernel(const float* __restrict__ Q, const float* __restrict__ Kg,
            const float* __restrict__ Vg, float* __restrict__ O)
{
    extern __shared__ float smf[];
    float* Qs = smf;                   // [64][132]
    float* Ks = Qs + 64 * QPAD;        // [64][132]
    float* Vs = Ks + 64 * QPAD;        // [64][128]
    float* Ss = Vs + 64 * 128;         // [64][68]

    const int tid = threadIdx.x;
    const int qt = blockIdx.x;
    const int bh = blockIdx.y;
    const int q0 = qt * 64;
    const long base = (long)bh * Tp * Dp;

    for (int i = tid; i < 64 * 128; i += 256)
        Qs[(i >> 7) * QPAD + (i & 127)] = Q[base + (long)q0 * Dp + i];

    const int r  = tid >> 2;
    const int d0 = (tid & 3) * 32;
    const int sr = (tid >> 4) * 4;
    const int sc = (tid & 15) * 4;

    float acc[32];
#pragma unroll
    for (int i = 0; i < 32; i++) acc[i] = 0.f;
    float m_i = -1e30f, l_i = 0.f;

    for (int j = 0; j <= qt; j++) {
        __syncthreads();
        for (int i = tid; i < 64 * 128; i += 256) {
            int rr = i >> 7, cc = i & 127;
            Ks[rr * QPAD + cc] = Kg[base + (long)j * 64 * Dp + i];
            Vs[rr * 128 + cc] = Vg[base + (long)j * 64 * Dp + i];
        }
        __syncthreads();

        float s[4][4];
#pragma unroll
        for (int a = 0; a < 4; a++)
#pragma unroll
            for (int b = 0; b < 4; b++) s[a][b] = 0.f;

        for (int k = 0; k < 128; k += 4) {
            float4 q4[4], k4[4];
#pragma unroll
            for (int a = 0; a < 4; a++) q4[a] = *(const float4*)&Qs[(sr + a) * QPAD + k];
#pragma unroll
            for (int b = 0; b < 4; b++) k4[b] = *(const float4*)&Ks[(sc + b) * QPAD + k];
#pragma unroll
            for (int a = 0; a < 4; a++)
#pragma unroll
                for (int b = 0; b < 4; b++) {
                    s[a][b] += q4[a].x * k4[b].x;
                    s[a][b] += q4[a].y * k4[b].y;
                    s[a][b] += q4[a].z * k4[b].z;
                    s[a][b] += q4[a].w * k4[b].w;
                }
        }
#pragma unroll
        for (int a = 0; a < 4; a++) {
            float4 v;
            v.x = s[a][0] * SCALE; v.y = s[a][1] * SCALE;
            v.z = s[a][2] * SCALE; v.w = s[a][3] * SCALE;
            *(float4*)&Ss[(sr + a) * SPAD + sc] = v;
        }
        __syncthreads();

        const int climit = (j == qt) ? (r + 1) : 64;
        float mx = m_i;
        for (int c = 0; c < climit; c++) mx = fmaxf(mx, Ss[r * SPAD + c]);
        float corr = __expf(m_i - mx);
        m_i = mx;
        l_i *= corr;
#pragma unroll
        for (int i = 0; i < 32; i++) acc[i] *= corr;
        for (int c = 0; c < climit; c++) {
            float pv = __expf(Ss[r * SPAD + c] - mx);
            l_i += pv;
            const float* vrow = &Vs[c * 128 + d0];
#pragma unroll
            for (int i = 0; i < 8; i++) {
                float4 v4 = *(const float4*)&vrow[i * 4];
                acc[i * 4 + 0] += pv * v4.x;
                acc[i * 4 + 1] += pv * v4.y;
                acc[i * 4 + 2] += pv * v4.z;
                acc[i * 4 + 3] += pv * v4.w;
            }
        }
    }

    const float inv = 1.f / l_i;
    const int b = bh >> 4, h = bh & 15;
    const int t = q0 + r;
    float* op = O + ((long)(b * Tp + t) * Cp + h * Dp + d0);
#pragma unroll
    for (int i = 0; i < 8; i++) {
        float4 v4;
        v4.x = acc[i * 4 + 0] * inv; v4.y = acc[i * 4 + 1] * inv;
        v4.z = acc[i * 4 + 2] * inv; v4.w = acc[i * 4 + 3] * inv;
        *(float4*)&op[i * 4] = v4;
    }
}

// ---------------------------------------------------------------------------
extern "C" void kernel_launch(void* const* d_in, const int* in_sizes, int n_in,
                              void* d_out, int out_size)
{
    const float* x      = (const float*)d_in[0];  // [B,T,C]
    const float* W_attn = (const float*)d_in[1];  // [3C,C]
    const float* W_proj = (const float*)d_in[2];  // [C,C]
    float* out = (float*)d_out;                   // [B,T,C]

    float *pq, *pk, *pv, *pao;
    cudaGetSymbolAddress((void**)&pq,  g_q);
    cudaGetSymbolAddress((void**)&pk,  g_k);
    cudaGetSymbolAddress((void**)&pv,  g_v);
    cudaGetSymbolAddress((void**)&pao, g_ao);

    cudaFuncSetAttribute(attn_kernel,
                         cudaFuncAttributeMaxDynamicSharedMemorySize, ATTN_SMEM);

    // 1) QKV projection (tf32 mma.sync) with scatter into [B,H,T,d]
    {
        dim3 grid(3 * Cp / BN, BTp / BM);
        gemm_mma<1><<<grid, 256>>>(x, W_attn, pq, pk, pv, BTp, 3 * Cp, Cp);
    }
    // 2) causal flash attention -> g_ao [B,T,C]
    {
        dim3 grid(Tp / 64, BHp);
        attn_kernel<<<grid, 256, ATTN_SMEM>>>(pq, pk, pv, pao);
    }
    // 3) output projection (tf32 mma.sync)
    {
        dim3 grid(Cp / BN, BTp / BM);
        gemm_mma<0><<<grid, 256>>>(pao, W_proj, out, nullptr, nullptr, BTp, Cp, Cp);
    }
}

// round 6
// speedup vs baseline: 4.7844x; 3.6836x over previous
#include <cuda_runtime.h>
#include <cuda_bf16.h>
#include <cstdint>
#include <math.h>

// Problem shape (fixed)
#define Bp 4
#define Tp 2048
#define Cp 2048
#define Hp 16
#define Dp 128
#define BHp (Bp*Hp)        // 64
#define BTp (Bp*Tp)        // 8192
#define SCALE 0.08838834764831845f  // 1/sqrt(128)

// Scratch (device globals; allocation-free per harness rules)
__device__ float g_q [BHp * Tp * Dp];   // [B,H,T,d]
__device__ float g_k [BHp * Tp * Dp];
__device__ float g_v [BHp * Tp * Dp];
__device__ float g_ao[BTp * Cp];        // attention out, [B,T,C]

__device__ __forceinline__ uint32_t f2tf32(float x) {
    uint32_t r;
    asm("cvt.rna.tf32.f32 %0, %1;" : "=r"(r) : "f"(x));
    return r;
}

__device__ __forceinline__ void mma_tf32(float* d, const uint32_t* a, const uint32_t* b) {
    asm volatile(
        "mma.sync.aligned.m16n8k8.row.col.f32.tf32.tf32.f32 "
        "{%0,%1,%2,%3}, {%4,%5,%6,%7}, {%8,%9}, {%0,%1,%2,%3};"
        : "+f"(d[0]), "+f"(d[1]), "+f"(d[2]), "+f"(d[3])
        : "r"(a[0]), "r"(a[1]), "r"(a[2]), "r"(a[3]), "r"(b[0]), "r"(b[1]));
}

// ===========================================================================
// tf32 mma.sync GEMM (unchanged from R5):
// C[m][n] = sum_k A[m][k]*B[n][k]   (NT, both K-major)
// ===========================================================================
#define BM 128
#define BN 128
#define BK 16
#define KP 20

template <int EPI>
__global__ void __launch_bounds__(256)
gemm_mma(const float* __restrict__ A, const float* __restrict__ B,
         float* __restrict__ Cq, float* __restrict__ Ck, float* __restrict__ Cv,
         int M, int N, int K)
{
    __shared__ uint32_t As[2][BM][KP];
    __shared__ uint32_t Bs[2][BN][KP];

    const int tid = threadIdx.x;
    const int lane = tid & 31;
    const int wid = tid >> 5;
    const int wm = (wid & 1) * 64;
    const int wn = (wid >> 1) * 32;
    const int m0 = blockIdx.y * BM;
    const int n0 = blockIdx.x * BN;

    float acc[4][4][4];
#pragma unroll
    for (int i = 0; i < 4; i++)
#pragma unroll
        for (int j = 0; j < 4; j++)
#pragma unroll
            for (int q = 0; q < 4; q++) acc[i][j][q] = 0.f;

    const int NK = K / BK;

    float4 ra[2], rb[2];
#pragma unroll
    for (int i = 0; i < 2; i++) {
        int cid = tid + 256 * i; int r = cid >> 2, c4 = cid & 3;
        ra[i] = *(const float4*)(A + (long)(m0 + r) * K + c4 * 4);
        rb[i] = *(const float4*)(B + (long)(n0 + r) * K + c4 * 4);
    }
#pragma unroll
    for (int i = 0; i < 2; i++) {
        int cid = tid + 256 * i; int r = cid >> 2, c4 = cid & 3;
        uint4 ua, ub;
        ua.x = f2tf32(ra[i].x); ua.y = f2tf32(ra[i].y);
        ua.z = f2tf32(ra[i].z); ua.w = f2tf32(ra[i].w);
        ub.x = f2tf32(rb[i].x); ub.y = f2tf32(rb[i].y);
        ub.z = f2tf32(rb[i].z); ub.w = f2tf32(rb[i].w);
        *(uint4*)&As[0][r][c4 * 4] = ua;
        *(uint4*)&Bs[0][r][c4 * 4] = ub;
    }
    __syncthreads();

    const int ar = lane >> 2;
    const int ac = lane & 3;

    for (int kt = 0; kt < NK; kt++) {
        const int s = kt & 1;
        const bool havenext = (kt + 1 < NK);
        if (havenext) {
            const int ko = (kt + 1) * BK;
#pragma unroll
            for (int i = 0; i < 2; i++) {
                int cid = tid + 256 * i; int r = cid >> 2, c4 = cid & 3;
                ra[i] = *(const float4*)(A + (long)(m0 + r) * K + ko + c4 * 4);
                rb[i] = *(const float4*)(B + (long)(n0 + r) * K + ko + c4 * 4);
            }
        }

#pragma unroll
        for (int ks = 0; ks < 2; ks++) {
            const int kc = ks * 8;
            uint32_t af[4][4], bf[4][2];
#pragma unroll
            for (int i = 0; i < 4; i++) {
                const int rb_ = wm + i * 16;
                af[i][0] = As[s][rb_ + ar][kc + ac];
                af[i][1] = As[s][rb_ + ar + 8][kc + ac];
                af[i][2] = As[s][rb_ + ar][kc + ac + 4];
                af[i][3] = As[s][rb_ + ar + 8][kc + ac + 4];
            }
#pragma unroll
            for (int j = 0; j < 4; j++) {
                const int cb = wn + j * 8;
                bf[j][0] = Bs[s][cb + ar][kc + ac];
                bf[j][1] = Bs[s][cb + ar][kc + ac + 4];
            }
#pragma unroll
            for (int i = 0; i < 4; i++)
#pragma unroll
                for (int j = 0; j < 4; j++)
                    mma_tf32(acc[i][j], af[i], bf[j]);
        }

        if (havenext) {
            __syncthreads();
            const int z = s ^ 1;
#pragma unroll
            for (int i = 0; i < 2; i++) {
                int cid = tid + 256 * i; int r = cid >> 2, c4 = cid & 3;
                uint4 ua, ub;
                ua.x = f2tf32(ra[i].x); ua.y = f2tf32(ra[i].y);
                ua.z = f2tf32(ra[i].z); ua.w = f2tf32(ra[i].w);
                ub.x = f2tf32(rb[i].x); ub.y = f2tf32(rb[i].y);
                ub.z = f2tf32(rb[i].z); ub.w = f2tf32(rb[i].w);
                *(uint4*)&As[z][r][c4 * 4] = ua;
                *(uint4*)&Bs[z][r][c4 * 4] = ub;
            }
            __syncthreads();
        }
    }

#pragma unroll
    for (int i = 0; i < 4; i++) {
        const int mrow0 = m0 + wm + i * 16 + ar;
#pragma unroll
        for (int j = 0; j < 4; j++) {
            const int n = n0 + wn + j * 8 + ac * 2;
            if (EPI == 0) {
                float* d0 = Cq + (long)mrow0 * N + n;
                float* d1 = Cq + (long)(mrow0 + 8) * N + n;
                *(float2*)d0 = make_float2(acc[i][j][0], acc[i][j][1]);
                *(float2*)d1 = make_float2(acc[i][j][2], acc[i][j][3]);
            } else {
                const int which = n >> 11;
                const int rem = n & 2047;
                const int h = rem >> 7, dd = rem & 127;
                float* base = (which == 0) ? Cq : (which == 1) ? Ck : Cv;
                const int b0_ = mrow0 >> 11, t0 = mrow0 & 2047;
                const int b1_ = (mrow0 + 8) >> 11, t1 = (mrow0 + 8) & 2047;
                float* d0 = base + (((long)(b0_ * Hp + h) * Tp + t0) * Dp + dd);
                float* d1 = base + (((long)(b1_ * Hp + h) * Tp + t1) * Dp + dd);
                *(float2*)d0 = make_float2(acc[i][j][0], acc[i][j][1]);
                *(float2*)d1 = make_float2(acc[i][j][2], acc[i][j][3]);
            }
        }
    }
}

// ===========================================================================
// Tensor-core causal flash attention (tf32 mma.sync).
// Block: 128 queries, 8 warps (16 rows each). KV tile = 64.
// Smem (uint32): Qs[128][132], Ks[64][132], Vs[64][132], Ps[8][16][68]
// ===========================================================================
#define AQ_STR 132
#define KV_STR 132
#define P_STR  68
#define ATTN2_SMEM ((128*AQ_STR + 64*KV_STR + 64*KV_STR + 8*16*P_STR) * 4)

__global__ void __launch_bounds__(256)
attn_tc(const float* __restrict__ Qg, const float* __restrict__ Kg,
        const float* __restrict__ Vg, float* __restrict__ Og)
{
    extern __shared__ uint32_t sm[];
    uint32_t* Qs = sm;                       // [128][132]
    uint32_t* Ks = Qs + 128 * AQ_STR;        // [64][132]
    uint32_t* Vs = Ks + 64 * KV_STR;         // [64][132]
    uint32_t* Ps = Vs + 64 * KV_STR;         // [8][16][68]

    const int tid = threadIdx.x;
    const int lane = tid & 31;
    const int w = tid >> 5;
    const int g = lane >> 2;        // 0..7
    const int t4 = lane & 3;        // 0..3
    const int qt = gridDim.x - 1 - blockIdx.x;   // heavy tiles launch first
    const int bh = blockIdx.y;
    const int q0 = qt * 128;
    const long base = (long)bh * Tp * Dp;
    uint32_t* Pw = Ps + w * 16 * P_STR;

    // stage Q tile (tf32)
    for (int i = tid; i < 128 * 32; i += 256) {
        int r = i >> 5, c4 = i & 31;
        float4 v = *(const float4*)(Qg + base + (long)(q0 + r) * Dp + c4 * 4);
        uint4 u;
        u.x = f2tf32(v.x); u.y = f2tf32(v.y); u.z = f2tf32(v.z); u.w = f2tf32(v.w);
        *(uint4*)&Qs[r * AQ_STR + c4 * 4] = u;
    }

    float oacc[16][4];
#pragma unroll
    for (int i = 0; i < 16; i++)
#pragma unroll
        for (int q = 0; q < 4; q++) oacc[i][q] = 0.f;
    float m_lo = -1e30f, m_hi = -1e30f, l_lo = 0.f, l_hi = 0.f;

    const int row_lo = q0 + w * 16 + g;
    const int row_hi = row_lo + 8;
    const int njt = qt * 2 + 2;

    for (int j = 0; j < njt; j++) {
        __syncthreads();
        for (int i = tid; i < 64 * 32; i += 256) {
            int r = i >> 5, c4 = i & 31;
            float4 kv = *(const float4*)(Kg + base + (long)(j * 64 + r) * Dp + c4 * 4);
            float4 vv = *(const float4*)(Vg + base + (long)(j * 64 + r) * Dp + c4 * 4);
            uint4 uk, uv;
            uk.x = f2tf32(kv.x); uk.y = f2tf32(kv.y); uk.z = f2tf32(kv.z); uk.w = f2tf32(kv.w);
            uv.x = f2tf32(vv.x); uv.y = f2tf32(vv.y); uv.z = f2tf32(vv.z); uv.w = f2tf32(vv.w);
            *(uint4*)&Ks[r * KV_STR + c4 * 4] = uk;
            *(uint4*)&Vs[r * KV_STR + c4 * 4] = uv;
        }
        __syncthreads();

        // ---- S = Q K^T (warp rows 16, cols 64) ----
        float sf[8][4];
#pragma unroll
        for (int n = 0; n < 8; n++)
#pragma unroll
            for (int q = 0; q < 4; q++) sf[n][q] = 0.f;

#pragma unroll 4
        for (int kc = 0; kc < 16; kc++) {
            uint32_t af[4];
            const uint32_t* qrow = Qs + (w * 16) * AQ_STR + kc * 8;
            af[0] = qrow[g * AQ_STR + t4];
            af[1] = qrow[(g + 8) * AQ_STR + t4];
            af[2] = qrow[g * AQ_STR + t4 + 4];
            af[3] = qrow[(g + 8) * AQ_STR + t4 + 4];
#pragma unroll
            for (int n = 0; n < 8; n++) {
                uint32_t bf[2];
                const uint32_t* krow = Ks + (n * 8 + g) * KV_STR + kc * 8;
                bf[0] = krow[t4];
                bf[1] = krow[t4 + 4];
                mma_tf32(sf[n], af, bf);
            }
        }

        // ---- mask + scale ----
        if (j * 64 + 63 <= q0 + w * 16) {
#pragma unroll
            for (int n = 0; n < 8; n++)
#pragma unroll
                for (int q = 0; q < 4; q++) sf[n][q] *= SCALE;
        } else {
#pragma unroll
            for (int n = 0; n < 8; n++) {
                const int col = j * 64 + n * 8 + 2 * t4;
                sf[n][0] = (col     <= row_lo) ? sf[n][0] * SCALE : -1e30f;
                sf[n][1] = (col + 1 <= row_lo) ? sf[n][1] * SCALE : -1e30f;
                sf[n][2] = (col     <= row_hi) ? sf[n][2] * SCALE : -1e30f;
                sf[n][3] = (col + 1 <= row_hi) ? sf[n][3] * SCALE : -1e30f;
            }
        }

        // ---- online softmax ----
        float tl = -1e30f, th = -1e30f;
#pragma unroll
        for (int n = 0; n < 8; n++) {
            tl = fmaxf(tl, fmaxf(sf[n][0], sf[n][1]));
            th = fmaxf(th, fmaxf(sf[n][2], sf[n][3]));
        }
        tl = fmaxf(tl, __shfl_xor_sync(0xffffffffu, tl, 1));
        tl = fmaxf(tl, __shfl_xor_sync(0xffffffffu, tl, 2));
        th = fmaxf(th, __shfl_xor_sync(0xffffffffu, th, 1));
        th = fmaxf(th, __shfl_xor_sync(0xffffffffu, th, 2));
        const float mn_lo = fmaxf(m_lo, tl);
        const float mn_hi = fmaxf(m_hi, th);
        const float corr_lo = __expf(m_lo - mn_lo);
        const float corr_hi = __expf(m_hi - mn_hi);
        m_lo = mn_lo; m_hi = mn_hi;

        float sum_lo = 0.f, sum_hi = 0.f;
#pragma unroll
        for (int n = 0; n < 8; n++) {
            float p0 = __expf(sf[n][0] - m_lo);
            float p1 = __expf(sf[n][1] - m_lo);
            float p2 = __expf(sf[n][2] - m_hi);
            float p3 = __expf(sf[n][3] - m_hi);
            sum_lo += p0 + p1;
            sum_hi += p2 + p3;
            const int pc = n * 8 + 2 * t4;
            Pw[g * P_STR + pc]           = f2tf32(p0);
            Pw[g * P_STR + pc + 1]       = f2tf32(p1);
            Pw[(g + 8) * P_STR + pc]     = f2tf32(p2);
            Pw[(g + 8) * P_STR + pc + 1] = f2tf32(p3);
        }
        sum_lo += __shfl_xor_sync(0xffffffffu, sum_lo, 1);
        sum_lo += __shfl_xor_sync(0xffffffffu, sum_lo, 2);
        sum_hi += __shfl_xor_sync(0xffffffffu, sum_hi, 1);
        sum_hi += __shfl_xor_sync(0xffffffffu, sum_hi, 2);
        l_lo = l_lo * corr_lo + sum_lo;
        l_hi = l_hi * corr_hi + sum_hi;
#pragma unroll
        for (int dt = 0; dt < 16; dt++) {
            oacc[dt][0] *= corr_lo; oacc[dt][1] *= corr_lo;
            oacc[dt][2] *= corr_hi; oacc[dt][3] *= corr_hi;
        }
        __syncwarp();

        // ---- O += P V ----
        uint32_t paf[8][4];
#pragma unroll
        for (int kc = 0; kc < 8; kc++) {
            paf[kc][0] = Pw[g * P_STR + kc * 8 + t4];
            paf[kc][1] = Pw[(g + 8) * P_STR + kc * 8 + t4];
            paf[kc][2] = Pw[g * P_STR + kc * 8 + t4 + 4];
            paf[kc][3] = Pw[(g + 8) * P_STR + kc * 8 + t4 + 4];
        }
#pragma unroll 2
        for (int dt = 0; dt < 16; dt++) {
#pragma unroll
            for (int kc = 0; kc < 8; kc++) {
                uint32_t bf[2];
                bf[0] = Vs[(kc * 8 + t4) * KV_STR + dt * 8 + g];
                bf[1] = Vs[(kc * 8 + t4 + 4) * KV_STR + dt * 8 + g];
                mma_tf32(oacc[dt], paf[kc], bf);
            }
        }
    }

    // ---- epilogue ----
    const float il_lo = 1.f / l_lo;
    const float il_hi = 1.f / l_hi;
    const int b = bh >> 4, h = bh & 15;
    float* o_lo = Og + ((long)(b * Tp + row_lo)) * Cp + h * Dp;
    float* o_hi = Og + ((long)(b * Tp + row_hi)) * Cp + h * Dp;
#pragma unroll
    for (int dt = 0; dt < 16; dt++) {
        const int col = dt * 8 + 2 * t4;
        *(float2*)(o_lo + col) = make_float2(oacc[dt][0] * il_lo, oacc[dt][1] * il_lo);
        *(float2*)(o_hi + col) = make_float2(oacc[dt][2] * il_hi, oacc[dt][3] * il_hi);
    }
}

// ---------------------------------------------------------------------------
extern "C" void kernel_launch(void* const* d_in, const int* in_sizes, int n_in,
                              void* d_out, int out_size)
{
    const float* x      = (const float*)d_in[0];  // [B,T,C]
    const float* W_attn = (const float*)d_in[1];  // [3C,C]
    const float* W_proj = (const float*)d_in[2];  // [C,C]
    float* out = (float*)d_out;                   // [B,T,C]

    float *pq, *pk, *pv, *pao;
    cudaGetSymbolAddress((void**)&pq,  g_q);
    cudaGetSymbolAddress((void**)&pk,  g_k);
    cudaGetSymbolAddress((void**)&pv,  g_v);
    cudaGetSymbolAddress((void**)&pao, g_ao);

    cudaFuncSetAttribute(attn_tc,
                         cudaFuncAttributeMaxDynamicSharedMemorySize, ATTN2_SMEM);

    // 1) QKV projection (tf32 mma.sync) with scatter into [B,H,T,d]
    {
        dim3 grid(3 * Cp / BN, BTp / BM);
        gemm_mma<1><<<grid, 256>>>(x, W_attn, pq, pk, pv, BTp, 3 * Cp, Cp);
    }
    // 2) tensor-core causal flash attention -> g_ao [B,T,C]
    {
        dim3 grid(Tp / 128, BHp);
        attn_tc<<<grid, 256, ATTN2_SMEM>>>(pq, pk, pv, pao);
    }
    // 3) output projection (tf32 mma.sync)
    {
        dim3 grid(Cp / BN, BTp / BM);
        gemm_mma<0><<<grid, 256>>>(pao, W_proj, out, nullptr, nullptr, BTp, Cp, Cp);
    }
}

// round 7
// speedup vs baseline: 5.3800x; 1.1245x over previous
#include <cuda_runtime.h>
#include <cuda_bf16.h>
#include <cstdint>
#include <math.h>

// Problem shape (fixed)
#define Bp 4
#define Tp 2048
#define Cp 2048
#define Hp 16
#define Dp 128
#define BHp (Bp*Hp)        // 64
#define BTp (Bp*Tp)        // 8192
#define SCALE 0.08838834764831845f  // 1/sqrt(128)

// Scratch (device globals; allocation-free per harness rules)
__device__ float g_q [BHp * Tp * Dp];   // [B,H,T,d]
__device__ float g_k [BHp * Tp * Dp];
__device__ float g_v [BHp * Tp * Dp];
__device__ float g_ao[BTp * Cp];        // attention out, [B,T,C]

__device__ __forceinline__ uint32_t f2tf32(float x) {
    uint32_t r;
    asm("cvt.rna.tf32.f32 %0, %1;" : "=r"(r) : "f"(x));
    return r;
}

__device__ __forceinline__ void mma_tf32(float* d, const uint32_t* a, const uint32_t* b) {
    asm volatile(
        "mma.sync.aligned.m16n8k8.row.col.f32.tf32.tf32.f32 "
        "{%0,%1,%2,%3}, {%4,%5,%6,%7}, {%8,%9}, {%0,%1,%2,%3};"
        : "+f"(d[0]), "+f"(d[1]), "+f"(d[2]), "+f"(d[3])
        : "r"(a[0]), "r"(a[1]), "r"(a[2]), "r"(a[3]), "r"(b[0]), "r"(b[1]));
}

// ===========================================================================
// tf32 mma.sync GEMM:  C[m][n] = sum_k A[m][k]*B[n][k]   (NT, both K-major)
// BM=BN=128, BK=16. 128 threads (4 warps, 2x2), warp tile 64x64.
// Double-buffered smem, tf32 conversion on the STS path, register prefetch.
// EPI=0: row-major store. EPI=1: qkv scatter to [B,H,T,d].
// ===========================================================================
#define BM 128
#define BN 128
#define BK 16
#define KP 20   // BK + 4 pad -> conflict-free fragment LDS (stride 20 mod 32 pattern)

template <int EPI>
__global__ void __launch_bounds__(128, 2)
gemm_mma(const float* __restrict__ A, const float* __restrict__ B,
         float* __restrict__ Cq, float* __restrict__ Ck, float* __restrict__ Cv,
         int M, int N, int K)
{
    __shared__ uint32_t As[2][BM][KP];
    __shared__ uint32_t Bs[2][BN][KP];

    const int tid = threadIdx.x;
    const int lane = tid & 31;
    const int wid = tid >> 5;            // 0..3
    const int wm = (wid & 1) * 64;       // warp m offset
    const int wn = (wid >> 1) * 64;      // warp n offset
    const int m0 = blockIdx.y * BM;
    const int n0 = blockIdx.x * BN;

    float acc[4][8][4];
#pragma unroll
    for (int i = 0; i < 4; i++)
#pragma unroll
        for (int j = 0; j < 8; j++)
#pragma unroll
            for (int q = 0; q < 4; q++) acc[i][j][q] = 0.f;

    const int NK = K / BK;

    float4 ra[4], rb[4];
    // prologue: tile 0
#pragma unroll
    for (int i = 0; i < 4; i++) {
        int cid = tid + 128 * i; int r = cid >> 2, c4 = cid & 3;
        ra[i] = *(const float4*)(A + (long)(m0 + r) * K + c4 * 4);
        rb[i] = *(const float4*)(B + (long)(n0 + r) * K + c4 * 4);
    }
#pragma unroll
    for (int i = 0; i < 4; i++) {
        int cid = tid + 128 * i; int r = cid >> 2, c4 = cid & 3;
        uint4 ua, ub;
        ua.x = f2tf32(ra[i].x); ua.y = f2tf32(ra[i].y);
        ua.z = f2tf32(ra[i].z); ua.w = f2tf32(ra[i].w);
        ub.x = f2tf32(rb[i].x); ub.y = f2tf32(rb[i].y);
        ub.z = f2tf32(rb[i].z); ub.w = f2tf32(rb[i].w);
        *(uint4*)&As[0][r][c4 * 4] = ua;
        *(uint4*)&Bs[0][r][c4 * 4] = ub;
    }
    __syncthreads();

    const int ar = lane >> 2;   // 0..7
    const int ac = lane & 3;    // 0..3

    for (int kt = 0; kt < NK; kt++) {
        const int s = kt & 1;
        const bool havenext = (kt + 1 < NK);
        if (havenext) {
            const int ko = (kt + 1) * BK;
#pragma unroll
            for (int i = 0; i < 4; i++) {
                int cid = tid + 128 * i; int r = cid >> 2, c4 = cid & 3;
                ra[i] = *(const float4*)(A + (long)(m0 + r) * K + ko + c4 * 4);
                rb[i] = *(const float4*)(B + (long)(n0 + r) * K + ko + c4 * 4);
            }
        }

#pragma unroll
        for (int ks = 0; ks < 2; ks++) {
            const int kc = ks * 8;
            uint32_t af[4][4], bf[8][2];
#pragma unroll
            for (int i = 0; i < 4; i++) {
                const int rb_ = wm + i * 16;
                af[i][0] = As[s][rb_ + ar][kc + ac];
                af[i][1] = As[s][rb_ + ar + 8][kc + ac];
                af[i][2] = As[s][rb_ + ar][kc + ac + 4];
                af[i][3] = As[s][rb_ + ar + 8][kc + ac + 4];
            }
#pragma unroll
            for (int j = 0; j < 8; j++) {
                const int cb = wn + j * 8;
                bf[j][0] = Bs[s][cb + ar][kc + ac];
                bf[j][1] = Bs[s][cb + ar][kc + ac + 4];
            }
#pragma unroll
            for (int i = 0; i < 4; i++)
#pragma unroll
                for (int j = 0; j < 8; j++)
                    mma_tf32(acc[i][j], af[i], bf[j]);
        }

        if (havenext) {
            __syncthreads();
            const int z = s ^ 1;
#pragma unroll
            for (int i = 0; i < 4; i++) {
                int cid = tid + 128 * i; int r = cid >> 2, c4 = cid & 3;
                uint4 ua, ub;
                ua.x = f2tf32(ra[i].x); ua.y = f2tf32(ra[i].y);
                ua.z = f2tf32(ra[i].z); ua.w = f2tf32(ra[i].w);
                ub.x = f2tf32(rb[i].x); ub.y = f2tf32(rb[i].y);
                ub.z = f2tf32(rb[i].z); ub.w = f2tf32(rb[i].w);
                *(uint4*)&As[z][r][c4 * 4] = ua;
                *(uint4*)&Bs[z][r][c4 * 4] = ub;
            }
            __syncthreads();
        }
    }

    // Epilogue: c0,c1 at (row=ar, col=2*ac), c2,c3 at (row=ar+8, col=2*ac)
#pragma unroll
    for (int i = 0; i < 4; i++) {
        const int mrow0 = m0 + wm + i * 16 + ar;
#pragma unroll
        for (int j = 0; j < 8; j++) {
            const int n = n0 + wn + j * 8 + ac * 2;
            if (EPI == 0) {
                float* d0 = Cq + (long)mrow0 * N + n;
                float* d1 = Cq + (long)(mrow0 + 8) * N + n;
                *(float2*)d0 = make_float2(acc[i][j][0], acc[i][j][1]);
                *(float2*)d1 = make_float2(acc[i][j][2], acc[i][j][3]);
            } else {
                const int which = n >> 11;
                const int rem = n & 2047;
                const int h = rem >> 7, dd = rem & 127;
                float* base = (which == 0) ? Cq : (which == 1) ? Ck : Cv;
                const int b0_ = mrow0 >> 11, t0 = mrow0 & 2047;
                const int b1_ = (mrow0 + 8) >> 11, t1 = (mrow0 + 8) & 2047;
                float* d0 = base + (((long)(b0_ * Hp + h) * Tp + t0) * Dp + dd);
                float* d1 = base + (((long)(b1_ * Hp + h) * Tp + t1) * Dp + dd);
                *(float2*)d0 = make_float2(acc[i][j][0], acc[i][j][1]);
                *(float2*)d1 = make_float2(acc[i][j][2], acc[i][j][3]);
            }
        }
    }
}

// ===========================================================================
// Tensor-core causal flash attention (tf32 mma.sync). Unchanged from R6.
// Block: 128 queries, 8 warps (16 rows each). KV tile = 64.
// ===========================================================================
#define AQ_STR 132
#define KV_STR 132
#define P_STR  68
#define ATTN2_SMEM ((128*AQ_STR + 64*KV_STR + 64*KV_STR + 8*16*P_STR) * 4)

__global__ void __launch_bounds__(256)
attn_tc(const float* __restrict__ Qg, const float* __restrict__ Kg,
        const float* __restrict__ Vg, float* __restrict__ Og)
{
    extern __shared__ uint32_t sm[];
    uint32_t* Qs = sm;                       // [128][132]
    uint32_t* Ks = Qs + 128 * AQ_STR;        // [64][132]
    uint32_t* Vs = Ks + 64 * KV_STR;         // [64][132]
    uint32_t* Ps = Vs + 64 * KV_STR;         // [8][16][68]

    const int tid = threadIdx.x;
    const int lane = tid & 31;
    const int w = tid >> 5;
    const int g = lane >> 2;        // 0..7
    const int t4 = lane & 3;        // 0..3
    const int qt = gridDim.x - 1 - blockIdx.x;   // heavy tiles launch first
    const int bh = blockIdx.y;
    const int q0 = qt * 128;
    const long base = (long)bh * Tp * Dp;
    uint32_t* Pw = Ps + w * 16 * P_STR;

    for (int i = tid; i < 128 * 32; i += 256) {
        int r = i >> 5, c4 = i & 31;
        float4 v = *(const float4*)(Qg + base + (long)(q0 + r) * Dp + c4 * 4);
        uint4 u;
        u.x = f2tf32(v.x); u.y = f2tf32(v.y); u.z = f2tf32(v.z); u.w = f2tf32(v.w);
        *(uint4*)&Qs[r * AQ_STR + c4 * 4] = u;
    }

    float oacc[16][4];
#pragma unroll
    for (int i = 0; i < 16; i++)
#pragma unroll
        for (int q = 0; q < 4; q++) oacc[i][q] = 0.f;
    float m_lo = -1e30f, m_hi = -1e30f, l_lo = 0.f, l_hi = 0.f;

    const int row_lo = q0 + w * 16 + g;
    const int row_hi = row_lo + 8;
    const int njt = qt * 2 + 2;

    for (int j = 0; j < njt; j++) {
        __syncthreads();
        for (int i = tid; i < 64 * 32; i += 256) {
            int r = i >> 5, c4 = i & 31;
            float4 kv = *(const float4*)(Kg + base + (long)(j * 64 + r) * Dp + c4 * 4);
            float4 vv = *(const float4*)(Vg + base + (long)(j * 64 + r) * Dp + c4 * 4);
            uint4 uk, uv;
            uk.x = f2tf32(kv.x); uk.y = f2tf32(kv.y); uk.z = f2tf32(kv.z); uk.w = f2tf32(kv.w);
            uv.x = f2tf32(vv.x); uv.y = f2tf32(vv.y); uv.z = f2tf32(vv.z); uv.w = f2tf32(vv.w);
            *(uint4*)&Ks[r * KV_STR + c4 * 4] = uk;
            *(uint4*)&Vs[r * KV_STR + c4 * 4] = uv;
        }
        __syncthreads();

        float sf[8][4];
#pragma unroll
        for (int n = 0; n < 8; n++)
#pragma unroll
            for (int q = 0; q < 4; q++) sf[n][q] = 0.f;

#pragma unroll 4
        for (int kc = 0; kc < 16; kc++) {
            uint32_t af[4];
            const uint32_t* qrow = Qs + (w * 16) * AQ_STR + kc * 8;
            af[0] = qrow[g * AQ_STR + t4];
            af[1] = qrow[(g + 8) * AQ_STR + t4];
            af[2] = qrow[g * AQ_STR + t4 + 4];
            af[3] = qrow[(g + 8) * AQ_STR + t4 + 4];
#pragma unroll
            for (int n = 0; n < 8; n++) {
                uint32_t bf[2];
                const uint32_t* krow = Ks + (n * 8 + g) * KV_STR + kc * 8;
                bf[0] = krow[t4];
                bf[1] = krow[t4 + 4];
                mma_tf32(sf[n], af, bf);
            }
        }

        if (j * 64 + 63 <= q0 + w * 16) {
#pragma unroll
            for (int n = 0; n < 8; n++)
#pragma unroll
                for (int q = 0; q < 4; q++) sf[n][q] *= SCALE;
        } else {
#pragma unroll
            for (int n = 0; n < 8; n++) {
                const int col = j * 64 + n * 8 + 2 * t4;
                sf[n][0] = (col     <= row_lo) ? sf[n][0] * SCALE : -1e30f;
                sf[n][1] = (col + 1 <= row_lo) ? sf[n][1] * SCALE : -1e30f;
                sf[n][2] = (col     <= row_hi) ? sf[n][2] * SCALE : -1e30f;
                sf[n][3] = (col + 1 <= row_hi) ? sf[n][3] * SCALE : -1e30f;
            }
        }

        float tl = -1e30f, th = -1e30f;
#pragma unroll
        for (int n = 0; n < 8; n++) {
            tl = fmaxf(tl, fmaxf(sf[n][0], sf[n][1]));
            th = fmaxf(th, fmaxf(sf[n][2], sf[n][3]));
        }
        tl = fmaxf(tl, __shfl_xor_sync(0xffffffffu, tl, 1));
        tl = fmaxf(tl, __shfl_xor_sync(0xffffffffu, tl, 2));
        th = fmaxf(th, __shfl_xor_sync(0xffffffffu, th, 1));
        th = fmaxf(th, __shfl_xor_sync(0xffffffffu, th, 2));
        const float mn_lo = fmaxf(m_lo, tl);
        const float mn_hi = fmaxf(m_hi, th);
        const float corr_lo = __expf(m_lo - mn_lo);
        const float corr_hi = __expf(m_hi - mn_hi);
        m_lo = mn_lo; m_hi = mn_hi;

        float sum_lo = 0.f, sum_hi = 0.f;
#pragma unroll
        for (int n = 0; n < 8; n++) {
            float p0 = __expf(sf[n][0] - m_lo);
            float p1 = __expf(sf[n][1] - m_lo);
            float p2 = __expf(sf[n][2] - m_hi);
            float p3 = __expf(sf[n][3] - m_hi);
            sum_lo += p0 + p1;
            sum_hi += p2 + p3;
            const int pc = n * 8 + 2 * t4;
            Pw[g * P_STR + pc]           = f2tf32(p0);
            Pw[g * P_STR + pc + 1]       = f2tf32(p1);
            Pw[(g + 8) * P_STR + pc]     = f2tf32(p2);
            Pw[(g + 8) * P_STR + pc + 1] = f2tf32(p3);
        }
        sum_lo += __shfl_xor_sync(0xffffffffu, sum_lo, 1);
        sum_lo += __shfl_xor_sync(0xffffffffu, sum_lo, 2);
        sum_hi += __shfl_xor_sync(0xffffffffu, sum_hi, 1);
        sum_hi += __shfl_xor_sync(0xffffffffu, sum_hi, 2);
        l_lo = l_lo * corr_lo + sum_lo;
        l_hi = l_hi * corr_hi + sum_hi;
#pragma unroll
        for (int dt = 0; dt < 16; dt++) {
            oacc[dt][0] *= corr_lo; oacc[dt][1] *= corr_lo;
            oacc[dt][2] *= corr_hi; oacc[dt][3] *= corr_hi;
        }
        __syncwarp();

        uint32_t paf[8][4];
#pragma unroll
        for (int kc = 0; kc < 8; kc++) {
            paf[kc][0] = Pw[g * P_STR + kc * 8 + t4];
            paf[kc][1] = Pw[(g + 8) * P_STR + kc * 8 + t4];
            paf[kc][2] = Pw[g * P_STR + kc * 8 + t4 + 4];
            paf[kc][3] = Pw[(g + 8) * P_STR + kc * 8 + t4 + 4];
        }
#pragma unroll 2
        for (int dt = 0; dt < 16; dt++) {
#pragma unroll
            for (int kc = 0; kc < 8; kc++) {
                uint32_t bf[2];
                bf[0] = Vs[(kc * 8 + t4) * KV_STR + dt * 8 + g];
                bf[1] = Vs[(kc * 8 + t4 + 4) * KV_STR + dt * 8 + g];
                mma_tf32(oacc[dt], paf[kc], bf);
            }
        }
    }

    const float il_lo = 1.f / l_lo;
    const float il_hi = 1.f / l_hi;
    const int b = bh >> 4, h = bh & 15;
    float* o_lo = Og + ((long)(b * Tp + row_lo)) * Cp + h * Dp;
    float* o_hi = Og + ((long)(b * Tp + row_hi)) * Cp + h * Dp;
#pragma unroll
    for (int dt = 0; dt < 16; dt++) {
        const int col = dt * 8 + 2 * t4;
        *(float2*)(o_lo + col) = make_float2(oacc[dt][0] * il_lo, oacc[dt][1] * il_lo);
        *(float2*)(o_hi + col) = make_float2(oacc[dt][2] * il_hi, oacc[dt][3] * il_hi);
    }
}

// ---------------------------------------------------------------------------
extern "C" void kernel_launch(void* const* d_in, const int* in_sizes, int n_in,
                              void* d_out, int out_size)
{
    const float* x      = (const float*)d_in[0];  // [B,T,C]
    const float* W_attn = (const float*)d_in[1];  // [3C,C]
    const float* W_proj = (const float*)d_in[2];  // [C,C]
    float* out = (float*)d_out;                   // [B,T,C]

    float *pq, *pk, *pv, *pao;
    cudaGetSymbolAddress((void**)&pq,  g_q);
    cudaGetSymbolAddress((void**)&pk,  g_k);
    cudaGetSymbolAddress((void**)&pv,  g_v);
    cudaGetSymbolAddress((void**)&pao, g_ao);

    cudaFuncSetAttribute(attn_tc,
                         cudaFuncAttributeMaxDynamicSharedMemorySize, ATTN2_SMEM);

    // 1) QKV projection (tf32 mma.sync) with scatter into [B,H,T,d]
    {
        dim3 grid(3 * Cp / BN, BTp / BM);
        gemm_mma<1><<<grid, 128>>>(x, W_attn, pq, pk, pv, BTp, 3 * Cp, Cp);
    }
    // 2) tensor-core causal flash attention -> g_ao [B,T,C]
    {
        dim3 grid(Tp / 128, BHp);
        attn_tc<<<grid, 256, ATTN2_SMEM>>>(pq, pk, pv, pao);
    }
    // 3) output projection (tf32 mma.sync)
    {
        dim3 grid(Cp / BN, BTp / BM);
        gemm_mma<0><<<grid, 128>>>(pao, W_proj, out, nullptr, nullptr, BTp, Cp, Cp);
    }
}

// round 8
// speedup vs baseline: 5.8244x; 1.0826x over previous
#include <cuda_runtime.h>
#include <cuda_bf16.h>
#include <cstdint>
#include <math.h>

// Problem shape (fixed)
#define Bp 4
#define Tp 2048
#define Cp 2048
#define Hp 16
#define Dp 128
#define BHp (Bp*Hp)        // 64
#define BTp (Bp*Tp)        // 8192
#define SCALE 0.08838834764831845f  // 1/sqrt(128)

// Scratch (device globals; allocation-free per harness rules)
__device__ float g_q [BHp * Tp * Dp];   // [B,H,T,d]
__device__ float g_k [BHp * Tp * Dp];
__device__ float g_v [BHp * Tp * Dp];
__device__ float g_ao[BTp * Cp];        // attention out, [B,T,C]

__device__ __forceinline__ uint32_t f2tf32(float x) {
    uint32_t r;
    asm("cvt.rna.tf32.f32 %0, %1;" : "=r"(r) : "f"(x));
    return r;
}

__device__ __forceinline__ void mma_tf32(float* d, const uint32_t* a, const uint32_t* b) {
    asm volatile(
        "mma.sync.aligned.m16n8k8.row.col.f32.tf32.tf32.f32 "
        "{%0,%1,%2,%3}, {%4,%5,%6,%7}, {%8,%9}, {%0,%1,%2,%3};"
        : "+f"(d[0]), "+f"(d[1]), "+f"(d[2]), "+f"(d[3])
        : "r"(a[0]), "r"(a[1]), "r"(a[2]), "r"(a[3]), "r"(b[0]), "r"(b[1]));
}

__device__ __forceinline__ void ldsm_x4(uint32_t* r, uint32_t addr) {
    asm volatile("ldmatrix.sync.aligned.m8n8.x4.shared.b16 {%0,%1,%2,%3}, [%4];"
                 : "=r"(r[0]), "=r"(r[1]), "=r"(r[2]), "=r"(r[3]) : "r"(addr));
}

// ===========================================================================
// tf32 mma.sync GEMM:  C[m][n] = sum_k A[m][k]*B[n][k]   (NT, both K-major)
// BM=BN=128, BK=16. 128 threads (4 warps, 2x2), warp tile 64x64.
// Double-buffered smem, tf32 conversion on the STS path, register prefetch,
// ldmatrix.x4 fragment loads.
// EPI=0: row-major store. EPI=1: qkv scatter to [B,H,T,d].
// ===========================================================================
#define BM 128
#define BN 128
#define BK 16
#define KP 20                      // row stride (uint32) -> 80B rows, LDSM conflict-free
#define STG_U32 (BM*KP)            // one stage of As (==Bs) in uint32
#define STG_BYTES (STG_U32*4)      // 10240

template <int EPI>
__global__ void __launch_bounds__(128, 2)
gemm_mma(const float* __restrict__ A, const float* __restrict__ B,
         float* __restrict__ Cq, float* __restrict__ Ck, float* __restrict__ Cv,
         int M, int N, int K)
{
    __shared__ uint32_t As[2][BM][KP];
    __shared__ uint32_t Bs[2][BN][KP];

    const int tid = threadIdx.x;
    const int lane = tid & 31;
    const int wid = tid >> 5;            // 0..3
    const int wm = (wid & 1) * 64;       // warp m offset
    const int wn = (wid >> 1) * 64;      // warp n offset
    const int m0 = blockIdx.y * BM;
    const int n0 = blockIdx.x * BN;

    float acc[4][8][4];
#pragma unroll
    for (int i = 0; i < 4; i++)
#pragma unroll
        for (int j = 0; j < 8; j++)
#pragma unroll
            for (int q = 0; q < 4; q++) acc[i][j][q] = 0.f;

    const int NK = K / BK;

    // ldmatrix per-lane addresses (stage 0)
    const uint32_t as0 = (uint32_t)__cvta_generic_to_shared(&As[0][0][0]);
    const uint32_t bs0 = (uint32_t)__cvta_generic_to_shared(&Bs[0][0][0]);
    const uint32_t a_addr = as0 + (((wm + (lane & 15)) * KP + ((lane >> 4) << 2)) << 2);
    const uint32_t b_addr = bs0 + (((wn + ((lane >> 4) << 3) + (lane & 7)) * KP
                                    + (((lane >> 3) & 1) << 2)) << 2);

    float4 ra[4], rb[4];
    // prologue: tile 0
#pragma unroll
    for (int i = 0; i < 4; i++) {
        int cid = tid + 128 * i; int r = cid >> 2, c4 = cid & 3;
        ra[i] = *(const float4*)(A + (long)(m0 + r) * K + c4 * 4);
        rb[i] = *(const float4*)(B + (long)(n0 + r) * K + c4 * 4);
    }
#pragma unroll
    for (int i = 0; i < 4; i++) {
        int cid = tid + 128 * i; int r = cid >> 2, c4 = cid & 3;
        uint4 ua, ub;
        ua.x = f2tf32(ra[i].x); ua.y = f2tf32(ra[i].y);
        ua.z = f2tf32(ra[i].z); ua.w = f2tf32(ra[i].w);
        ub.x = f2tf32(rb[i].x); ub.y = f2tf32(rb[i].y);
        ub.z = f2tf32(rb[i].z); ub.w = f2tf32(rb[i].w);
        *(uint4*)&As[0][r][c4 * 4] = ua;
        *(uint4*)&Bs[0][r][c4 * 4] = ub;
    }
    __syncthreads();

    for (int kt = 0; kt < NK; kt++) {
        const int s = kt & 1;
        const bool havenext = (kt + 1 < NK);
        if (havenext) {
            const int ko = (kt + 1) * BK;
#pragma unroll
            for (int i = 0; i < 4; i++) {
                int cid = tid + 128 * i; int r = cid >> 2, c4 = cid & 3;
                ra[i] = *(const float4*)(A + (long)(m0 + r) * K + ko + c4 * 4);
                rb[i] = *(const float4*)(B + (long)(n0 + r) * K + ko + c4 * 4);
            }
        }

        const uint32_t as_s = a_addr + s * STG_BYTES;
        const uint32_t bs_s = b_addr + s * STG_BYTES;
#pragma unroll
        for (int ks = 0; ks < 2; ks++) {
            const uint32_t kb = ks * 32;               // 8 cols * 4B
            uint32_t af[4][4], bf[8][2];
#pragma unroll
            for (int i = 0; i < 4; i++)
                ldsm_x4(af[i], as_s + kb + i * (16 * KP * 4));
#pragma unroll
            for (int jj = 0; jj < 4; jj++)
                ldsm_x4(&bf[jj * 2][0], bs_s + kb + jj * (16 * KP * 4));
#pragma unroll
            for (int i = 0; i < 4; i++)
#pragma unroll
                for (int j = 0; j < 8; j++)
                    mma_tf32(acc[i][j], af[i], bf[j]);
        }

        if (havenext) {
            __syncthreads();
            const int z = s ^ 1;
#pragma unroll
            for (int i = 0; i < 4; i++) {
                int cid = tid + 128 * i; int r = cid >> 2, c4 = cid & 3;
                uint4 ua, ub;
                ua.x = f2tf32(ra[i].x); ua.y = f2tf32(ra[i].y);
                ua.z = f2tf32(ra[i].z); ua.w = f2tf32(ra[i].w);
                ub.x = f2tf32(rb[i].x); ub.y = f2tf32(rb[i].y);
                ub.z = f2tf32(rb[i].z); ub.w = f2tf32(rb[i].w);
                *(uint4*)&As[z][r][c4 * 4] = ua;
                *(uint4*)&Bs[z][r][c4 * 4] = ub;
            }
            __syncthreads();
        }
    }

    const int ar = lane >> 2;
    const int ac = lane & 3;

    // Epilogue: c0,c1 at (row=ar, col=2*ac), c2,c3 at (row=ar+8, col=2*ac)
#pragma unroll
    for (int i = 0; i < 4; i++) {
        const int mrow0 = m0 + wm + i * 16 + ar;
#pragma unroll
        for (int j = 0; j < 8; j++) {
            const int n = n0 + wn + j * 8 + ac * 2;
            if (EPI == 0) {
                float* d0 = Cq + (long)mrow0 * N + n;
                float* d1 = Cq + (long)(mrow0 + 8) * N + n;
                *(float2*)d0 = make_float2(acc[i][j][0], acc[i][j][1]);
                *(float2*)d1 = make_float2(acc[i][j][2], acc[i][j][3]);
            } else {
                const int which = n >> 11;
                const int rem = n & 2047;
                const int h = rem >> 7, dd = rem & 127;
                float* base = (which == 0) ? Cq : (which == 1) ? Ck : Cv;
                const int b0_ = mrow0 >> 11, t0 = mrow0 & 2047;
                const int b1_ = (mrow0 + 8) >> 11, t1 = (mrow0 + 8) & 2047;
                float* d0 = base + (((long)(b0_ * Hp + h) * Tp + t0) * Dp + dd);
                float* d1 = base + (((long)(b1_ * Hp + h) * Tp + t1) * Dp + dd);
                *(float2*)d0 = make_float2(acc[i][j][0], acc[i][j][1]);
                *(float2*)d1 = make_float2(acc[i][j][2], acc[i][j][3]);
            }
        }
    }
}

// ===========================================================================
// Tensor-core causal flash attention (tf32 mma.sync). Unchanged from R6.
// Block: 128 queries, 8 warps (16 rows each). KV tile = 64.
// ===========================================================================
#define AQ_STR 132
#define KV_STR 132
#define P_STR  68
#define ATTN2_SMEM ((128*AQ_STR + 64*KV_STR + 64*KV_STR + 8*16*P_STR) * 4)

__global__ void __launch_bounds__(256)
attn_tc(const float* __restrict__ Qg, const float* __restrict__ Kg,
        const float* __restrict__ Vg, float* __restrict__ Og)
{
    extern __shared__ uint32_t sm[];
    uint32_t* Qs = sm;                       // [128][132]
    uint32_t* Ks = Qs + 128 * AQ_STR;        // [64][132]
    uint32_t* Vs = Ks + 64 * KV_STR;         // [64][132]
    uint32_t* Ps = Vs + 64 * KV_STR;         // [8][16][68]

    const int tid = threadIdx.x;
    const int lane = tid & 31;
    const int w = tid >> 5;
    const int g = lane >> 2;        // 0..7
    const int t4 = lane & 3;        // 0..3
    const int qt = gridDim.x - 1 - blockIdx.x;   // heavy tiles launch first
    const int bh = blockIdx.y;
    const int q0 = qt * 128;
    const long base = (long)bh * Tp * Dp;
    uint32_t* Pw = Ps + w * 16 * P_STR;

    for (int i = tid; i < 128 * 32; i += 256) {
        int r = i >> 5, c4 = i & 31;
        float4 v = *(const float4*)(Qg + base + (long)(q0 + r) * Dp + c4 * 4);
        uint4 u;
        u.x = f2tf32(v.x); u.y = f2tf32(v.y); u.z = f2tf32(v.z); u.w = f2tf32(v.w);
        *(uint4*)&Qs[r * AQ_STR + c4 * 4] = u;
    }

    float oacc[16][4];
#pragma unroll
    for (int i = 0; i < 16; i++)
#pragma unroll
        for (int q = 0; q < 4; q++) oacc[i][q] = 0.f;
    float m_lo = -1e30f, m_hi = -1e30f, l_lo = 0.f, l_hi = 0.f;

    const int row_lo = q0 + w * 16 + g;
    const int row_hi = row_lo + 8;
    const int njt = qt * 2 + 2;

    for (int j = 0; j < njt; j++) {
        __syncthreads();
        for (int i = tid; i < 64 * 32; i += 256) {
            int r = i >> 5, c4 = i & 31;
            float4 kv = *(const float4*)(Kg + base + (long)(j * 64 + r) * Dp + c4 * 4);
            float4 vv = *(const float4*)(Vg + base + (long)(j * 64 + r) * Dp + c4 * 4);
            uint4 uk, uv;
            uk.x = f2tf32(kv.x); uk.y = f2tf32(kv.y); uk.z = f2tf32(kv.z); uk.w = f2tf32(kv.w);
            uv.x = f2tf32(vv.x); uv.y = f2tf32(vv.y); uv.z = f2tf32(vv.z); uv.w = f2tf32(vv.w);
            *(uint4*)&Ks[r * KV_STR + c4 * 4] = uk;
            *(uint4*)&Vs[r * KV_STR + c4 * 4] = uv;
        }
        __syncthreads();

        float sf[8][4];
#pragma unroll
        for (int n = 0; n < 8; n++)
#pragma unroll
            for (int q = 0; q < 4; q++) sf[n][q] = 0.f;

#pragma unroll 4
        for (int kc = 0; kc < 16; kc++) {
            uint32_t af[4];
            const uint32_t* qrow = Qs + (w * 16) * AQ_STR + kc * 8;
            af[0] = qrow[g * AQ_STR + t4];
            af[1] = qrow[(g + 8) * AQ_STR + t4];
            af[2] = qrow[g * AQ_STR + t4 + 4];
            af[3] = qrow[(g + 8) * AQ_STR + t4 + 4];
#pragma unroll
            for (int n = 0; n < 8; n++) {
                uint32_t bf[2];
                const uint32_t* krow = Ks + (n * 8 + g) * KV_STR + kc * 8;
                bf[0] = krow[t4];
                bf[1] = krow[t4 + 4];
                mma_tf32(sf[n], af, bf);
            }
        }

        if (j * 64 + 63 <= q0 + w * 16) {
#pragma unroll
            for (int n = 0; n < 8; n++)
#pragma unroll
                for (int q = 0; q < 4; q++) sf[n][q] *= SCALE;
        } else {
#pragma unroll
            for (int n = 0; n < 8; n++) {
                const int col = j * 64 + n * 8 + 2 * t4;
                sf[n][0] = (col     <= row_lo) ? sf[n][0] * SCALE : -1e30f;
                sf[n][1] = (col + 1 <= row_lo) ? sf[n][1] * SCALE : -1e30f;
                sf[n][2] = (col     <= row_hi) ? sf[n][2] * SCALE : -1e30f;
                sf[n][3] = (col + 1 <= row_hi) ? sf[n][3] * SCALE : -1e30f;
            }
        }

        float tl = -1e30f, th = -1e30f;
#pragma unroll
        for (int n = 0; n < 8; n++) {
            tl = fmaxf(tl, fmaxf(sf[n][0], sf[n][1]));
            th = fmaxf(th, fmaxf(sf[n][2], sf[n][3]));
        }
        tl = fmaxf(tl, __shfl_xor_sync(0xffffffffu, tl, 1));
        tl = fmaxf(tl, __shfl_xor_sync(0xffffffffu, tl, 2));
        th = fmaxf(th, __shfl_xor_sync(0xffffffffu, th, 1));
        th = fmaxf(th, __shfl_xor_sync(0xffffffffu, th, 2));
        const float mn_lo = fmaxf(m_lo, tl);
        const float mn_hi = fmaxf(m_hi, th);
        const float corr_lo = __expf(m_lo - mn_lo);
        const float corr_hi = __expf(m_hi - mn_hi);
        m_lo = mn_lo; m_hi = mn_hi;

        float sum_lo = 0.f, sum_hi = 0.f;
#pragma unroll
        for (int n = 0; n < 8; n++) {
            float p0 = __expf(sf[n][0] - m_lo);
            float p1 = __expf(sf[n][1] - m_lo);
            float p2 = __expf(sf[n][2] - m_hi);
            float p3 = __expf(sf[n][3] - m_hi);
            sum_lo += p0 + p1;
            sum_hi += p2 + p3;
            const int pc = n * 8 + 2 * t4;
            Pw[g * P_STR + pc]           = f2tf32(p0);
            Pw[g * P_STR + pc + 1]       = f2tf32(p1);
            Pw[(g + 8) * P_STR + pc]     = f2tf32(p2);
            Pw[(g + 8) * P_STR + pc + 1] = f2tf32(p3);
        }
        sum_lo += __shfl_xor_sync(0xffffffffu, sum_lo, 1);
        sum_lo += __shfl_xor_sync(0xffffffffu, sum_lo, 2);
        sum_hi += __shfl_xor_sync(0xffffffffu, sum_hi, 1);
        sum_hi += __shfl_xor_sync(0xffffffffu, sum_hi, 2);
        l_lo = l_lo * corr_lo + sum_lo;
        l_hi = l_hi * corr_hi + sum_hi;
#pragma unroll
        for (int dt = 0; dt < 16; dt++) {
            oacc[dt][0] *= corr_lo; oacc[dt][1] *= corr_lo;
            oacc[dt][2] *= corr_hi; oacc[dt][3] *= corr_hi;
        }
        __syncwarp();

        uint32_t paf[8][4];
#pragma unroll
        for (int kc = 0; kc < 8; kc++) {
            paf[kc][0] = Pw[g * P_STR + kc * 8 + t4];
            paf[kc][1] = Pw[(g + 8) * P_STR + kc * 8 + t4];
            paf[kc][2] = Pw[g * P_STR + kc * 8 + t4 + 4];
            paf[kc][3] = Pw[(g + 8) * P_STR + kc * 8 + t4 + 4];
        }
#pragma unroll 2
        for (int dt = 0; dt < 16; dt++) {
#pragma unroll
            for (int kc = 0; kc < 8; kc++) {
                uint32_t bf[2];
                bf[0] = Vs[(kc * 8 + t4) * KV_STR + dt * 8 + g];
                bf[1] = Vs[(kc * 8 + t4 + 4) * KV_STR + dt * 8 + g];
                mma_tf32(oacc[dt], paf[kc], bf);
            }
        }
    }

    const float il_lo = 1.f / l_lo;
    const float il_hi = 1.f / l_hi;
    const int b = bh >> 4, h = bh & 15;
    float* o_lo = Og + ((long)(b * Tp + row_lo)) * Cp + h * Dp;
    float* o_hi = Og + ((long)(b * Tp + row_hi)) * Cp + h * Dp;
#pragma unroll
    for (int dt = 0; dt < 16; dt++) {
        const int col = dt * 8 + 2 * t4;
        *(float2*)(o_lo + col) = make_float2(oacc[dt][0] * il_lo, oacc[dt][1] * il_lo);
        *(float2*)(o_hi + col) = make_float2(oacc[dt][2] * il_hi, oacc[dt][3] * il_hi);
    }
}

// ---------------------------------------------------------------------------
extern "C" void kernel_launch(void* const* d_in, const int* in_sizes, int n_in,
                              void* d_out, int out_size)
{
    const float* x      = (const float*)d_in[0];  // [B,T,C]
    const float* W_attn = (const float*)d_in[1];  // [3C,C]
    const float* W_proj = (const float*)d_in[2];  // [C,C]
    float* out = (float*)d_out;                   // [B,T,C]

    float *pq, *pk, *pv, *pao;
    cudaGetSymbolAddress((void**)&pq,  g_q);
    cudaGetSymbolAddress((void**)&pk,  g_k);
    cudaGetSymbolAddress((void**)&pv,  g_v);
    cudaGetSymbolAddress((void**)&pao, g_ao);

    cudaFuncSetAttribute(attn_tc,
                         cudaFuncAttributeMaxDynamicSharedMemorySize, ATTN2_SMEM);

    // 1) QKV projection (tf32 mma.sync) with scatter into [B,H,T,d]
    {
        dim3 grid(3 * Cp / BN, BTp / BM);
        gemm_mma<1><<<grid, 128>>>(x, W_attn, pq, pk, pv, BTp, 3 * Cp, Cp);
    }
    // 2) tensor-core causal flash attention -> g_ao [B,T,C]
    {
        dim3 grid(Tp / 128, BHp);
        attn_tc<<<grid, 256, ATTN2_SMEM>>>(pq, pk, pv, pao);
    }
    // 3) output projection (tf32 mma.sync)
    {
        dim3 grid(Cp / BN, BTp / BM);
        gemm_mma<0><<<grid, 128>>>(pao, W_proj, out, nullptr, nullptr, BTp, Cp, Cp);
    }
}

// round 11
// speedup vs baseline: 6.2090x; 1.0660x over previous
#include <cuda_runtime.h>
#include <cuda_bf16.h>
#include <cstdint>
#include <math.h>

// Problem shape (fixed)
#define Bp 4
#define Tp 2048
#define Cp 2048
#define Hp 16
#define Dp 128
#define BHp (Bp*Hp)        // 64
#define BTp (Bp*Tp)        // 8192
#define SCALE 0.08838834764831845f  // 1/sqrt(128)

// Scratch (device globals; allocation-free per harness rules)
__device__ float g_q [BHp * Tp * Dp];   // [B,H,T,d]
__device__ float g_k [BHp * Tp * Dp];
__device__ float g_v [BHp * Tp * Dp];
__device__ float g_ao[BTp * Cp];        // attention out, [B,T,C] (tf32-rounded)
__device__ float g_xc[BTp * Cp];        // x, tf32-rounded
__device__ float g_wa[3 * Cp * Cp];     // W_attn, tf32-rounded
__device__ float g_wp[Cp * Cp];         // W_proj, tf32-rounded

__device__ __forceinline__ uint32_t f2tf32(float x) {
    uint32_t r;
    asm("cvt.rna.tf32.f32 %0, %1;" : "=r"(r) : "f"(x));
    return r;
}

__device__ __forceinline__ void mma_tf32(float* d, const uint32_t* a, const uint32_t* b) {
    asm volatile(
        "mma.sync.aligned.m16n8k8.row.col.f32.tf32.tf32.f32 "
        "{%0,%1,%2,%3}, {%4,%5,%6,%7}, {%8,%9}, {%0,%1,%2,%3};"
        : "+f"(d[0]), "+f"(d[1]), "+f"(d[2]), "+f"(d[3])
        : "r"(a[0]), "r"(a[1]), "r"(a[2]), "r"(a[3]), "r"(b[0]), "r"(b[1]));
}

__device__ __forceinline__ void ldsm_x4(uint32_t* r, uint32_t addr) {
    asm volatile("ldmatrix.sync.aligned.m8n8.x4.shared.b16 {%0,%1,%2,%3}, [%4];"
                 : "=r"(r[0]), "=r"(r[1]), "=r"(r[2]), "=r"(r[3]) : "r"(addr));
}

__device__ __forceinline__ void cp16(uint32_t saddr, const void* gaddr) {
    asm volatile("cp.async.cg.shared.global [%0], [%1], 16;"
                 :: "r"(saddr), "l"(gaddr) : "memory");
}
#define CP_COMMIT() asm volatile("cp.async.commit_group;" ::: "memory")
#define CP_WAIT(N)  asm volatile("cp.async.wait_group %0;" :: "n"(N) : "memory")

// ===========================================================================
// Elementwise tf32 rounding pre-pass (float4 vectorized)
// ===========================================================================
__global__ void cvt_tf32_kernel(const float4* __restrict__ in,
                                float4* __restrict__ out, int n4)
{
    int i = blockIdx.x * blockDim.x + threadIdx.x;
    if (i < n4) {
        float4 v = in[i];
        v.x = __uint_as_float(f2tf32(v.x));
        v.y = __uint_as_float(f2tf32(v.y));
        v.z = __uint_as_float(f2tf32(v.z));
        v.w = __uint_as_float(f2tf32(v.w));
        out[i] = v;
    }
}

// ===========================================================================
// tf32 mma.sync GEMM:  C[m][n] = sum_k A[m][k]*B[n][k]   (NT, both K-major)
// Inputs MUST already be tf32-rounded fp32. cp.async gmem->smem, double
// buffer, ldmatrix.x4 fragments. 128 threads (4 warps 2x2), warp tile 64x64.
// EPI=0: row-major store. EPI=1: qkv scatter to [B,H,T,d].
// ===========================================================================
#define BM 128
#define BN 128
#define BK 16
#define KP 20                      // row stride (uint32) -> 80B rows, LDSM conflict-free
#define STG_U32 (BM*KP)
#define STG_BYTES (STG_U32*4)      // 10240

template <int EPI>
__global__ void __launch_bounds__(128, 2)
gemm_mma(const float* __restrict__ A, const float* __restrict__ B,
         float* __restrict__ Cq, float* __restrict__ Ck, float* __restrict__ Cv,
         int M, int N, int K)
{
    __shared__ uint32_t As[2][BM][KP];
    __shared__ uint32_t Bs[2][BN][KP];

    const int tid = threadIdx.x;
    const int lane = tid & 31;
    const int wid = tid >> 5;            // 0..3
    const int wm = (wid & 1) * 64;
    const int wn = (wid >> 1) * 64;
    const int m0 = blockIdx.y * BM;
    const int n0 = blockIdx.x * BN;

    float acc[4][8][4];
#pragma unroll
    for (int i = 0; i < 4; i++)
#pragma unroll
        for (int j = 0; j < 8; j++)
#pragma unroll
            for (int q = 0; q < 4; q++) acc[i][j][q] = 0.f;

    const int NK = K / BK;

    // copy assignment: 4 A-chunks + 4 B-chunks of 16B per thread
    const int cr = tid >> 2;             // base row 0..31 (x4 via +32*i)
    const int cc = tid & 3;              // 16B chunk within row
    const uint32_t as_sm = (uint32_t)__cvta_generic_to_shared(&As[0][0][0]);
    const uint32_t bs_sm = (uint32_t)__cvta_generic_to_shared(&Bs[0][0][0]);

    // ldmatrix per-lane addresses (stage 0)
    const uint32_t a_addr = as_sm + (((wm + (lane & 15)) * KP + ((lane >> 4) << 2)) << 2);
    const uint32_t b_addr = bs_sm + (((wn + ((lane >> 4) << 3) + (lane & 7)) * KP
                                      + (((lane >> 3) & 1) << 2)) << 2);

    const float* Agp = A + (long)(m0 + cr) * K + cc * 4;
    const float* Bgp = B + (long)(n0 + cr) * K + cc * 4;
    const long rowK32 = (long)32 * K;

#define ISSUE_STAGE(stg, kt_) do {                                          \
        const uint32_t asx = as_sm + (stg) * STG_BYTES + ((cr * KP + cc * 4) << 2); \
        const uint32_t bsx = bs_sm + (stg) * STG_BYTES + ((cr * KP + cc * 4) << 2); \
        const float* ag = Agp + (kt_) * BK;                                 \
        const float* bg = Bgp + (kt_) * BK;                                 \
        _Pragma("unroll")                                                   \
        for (int i_ = 0; i_ < 4; i_++) {                                    \
            cp16(asx + i_ * (32 * KP * 4), ag + i_ * rowK32);               \
            cp16(bsx + i_ * (32 * KP * 4), bg + i_ * rowK32);               \
        }                                                                   \
        CP_COMMIT();                                                        \
    } while (0)

    ISSUE_STAGE(0, 0);

    for (int kt = 0; kt < NK; kt++) {
        const int s = kt & 1;
        const bool havenext = (kt + 1 < NK);
        if (havenext) {
            ISSUE_STAGE(s ^ 1, kt + 1);
            CP_WAIT(1);
        } else {
            CP_WAIT(0);
        }
        __syncthreads();

        const uint32_t as_s = a_addr + s * STG_BYTES;
        const uint32_t bs_s = b_addr + s * STG_BYTES;
#pragma unroll
        for (int ks = 0; ks < 2; ks++) {
            const uint32_t kb = ks * 32;
            uint32_t af[4][4], bf[8][2];
#pragma unroll
            for (int i = 0; i < 4; i++)
                ldsm_x4(af[i], as_s + kb + i * (16 * KP * 4));
#pragma unroll
            for (int jj = 0; jj < 4; jj++)
                ldsm_x4(&bf[jj * 2][0], bs_s + kb + jj * (16 * KP * 4));
#pragma unroll
            for (int i = 0; i < 4; i++)
#pragma unroll
                for (int j = 0; j < 8; j++)
                    mma_tf32(acc[i][j], af[i], bf[j]);
        }
        __syncthreads();
    }
#undef ISSUE_STAGE

    const int ar = lane >> 2;
    const int ac = lane & 3;

#pragma unroll
    for (int i = 0; i < 4; i++) {
        const int mrow0 = m0 + wm + i * 16 + ar;
#pragma unroll
        for (int j = 0; j < 8; j++) {
            const int n = n0 + wn + j * 8 + ac * 2;
            if (EPI == 0) {
                float* d0 = Cq + (long)mrow0 * N + n;
                float* d1 = Cq + (long)(mrow0 + 8) * N + n;
                *(float2*)d0 = make_float2(acc[i][j][0], acc[i][j][1]);
                *(float2*)d1 = make_float2(acc[i][j][2], acc[i][j][3]);
            } else {
                const int which = n >> 11;
                const int rem = n & 2047;
                const int h = rem >> 7, dd = rem & 127;
                float* base = (which == 0) ? Cq : (which == 1) ? Ck : Cv;
                const int b0_ = mrow0 >> 11, t0 = mrow0 & 2047;
                const int b1_ = (mrow0 + 8) >> 11, t1 = (mrow0 + 8) & 2047;
                float* d0 = base + (((long)(b0_ * Hp + h) * Tp + t0) * Dp + dd);
                float* d1 = base + (((long)(b1_ * Hp + h) * Tp + t1) * Dp + dd);
                *(float2*)d0 = make_float2(acc[i][j][0], acc[i][j][1]);
                *(float2*)d1 = make_float2(acc[i][j][2], acc[i][j][3]);
            }
        }
    }
}

// ===========================================================================
// Tensor-core causal flash attention (tf32 mma.sync).
// Epilogue stores tf32-rounded fp32 (so the proj GEMM can skip conversion).
// ===========================================================================
#define AQ_STR 132
#define KV_STR 132
#define P_STR  68
#define ATTN2_SMEM ((128*AQ_STR + 64*KV_STR + 64*KV_STR + 8*16*P_STR) * 4)

__global__ void __launch_bounds__(256)
attn_tc(const float* __restrict__ Qg, const float* __restrict__ Kg,
        const float* __restrict__ Vg, float* __restrict__ Og)
{
    extern __shared__ uint32_t sm[];
    uint32_t* Qs = sm;                       // [128][132]
    uint32_t* Ks = Qs + 128 * AQ_STR;        // [64][132]
    uint32_t* Vs = Ks + 64 * KV_STR;         // [64][132]
    uint32_t* Ps = Vs + 64 * KV_STR;         // [8][16][68]

    const int tid = threadIdx.x;
    const int lane = tid & 31;
    const int w = tid >> 5;
    const int g = lane >> 2;
    const int t4 = lane & 3;
    const int qt = gridDim.x - 1 - blockIdx.x;
    const int bh = blockIdx.y;
    const int q0 = qt * 128;
    const long base = (long)bh * Tp * Dp;
    uint32_t* Pw = Ps + w * 16 * P_STR;

    for (int i = tid; i < 128 * 32; i += 256) {
        int r = i >> 5, c4 = i & 31;
        float4 v = *(const float4*)(Qg + base + (long)(q0 + r) * Dp + c4 * 4);
        uint4 u;
        u.x = f2tf32(v.x); u.y = f2tf32(v.y); u.z = f2tf32(v.z); u.w = f2tf32(v.w);
        *(uint4*)&Qs[r * AQ_STR + c4 * 4] = u;
    }

    float oacc[16][4];
#pragma unroll
    for (int i = 0; i < 16; i++)
#pragma unroll
        for (int q = 0; q < 4; q++) oacc[i][q] = 0.f;
    float m_lo = -1e30f, m_hi = -1e30f, l_lo = 0.f, l_hi = 0.f;

    const int row_lo = q0 + w * 16 + g;
    const int row_hi = row_lo + 8;
    const int njt = qt * 2 + 2;

    for (int j = 0; j < njt; j++) {
        __syncthreads();
        for (int i = tid; i < 64 * 32; i += 256) {
            int r = i >> 5, c4 = i & 31;
            float4 kv = *(const float4*)(Kg + base + (long)(j * 64 + r) * Dp + c4 * 4);
            float4 vv = *(const float4*)(Vg + base + (long)(j * 64 + r) * Dp + c4 * 4);
            uint4 uk, uv;
            uk.x = f2tf32(kv.x); uk.y = f2tf32(kv.y); uk.z = f2tf32(kv.z); uk.w = f2tf32(kv.w);
            uv.x = f2tf32(vv.x); uv.y = f2tf32(vv.y); uv.z = f2tf32(vv.z); uv.w = f2tf32(vv.w);
            *(uint4*)&Ks[r * KV_STR + c4 * 4] = uk;
            *(uint4*)&Vs[r * KV_STR + c4 * 4] = uv;
        }
        __syncthreads();

        float sf[8][4];
#pragma unroll
        for (int n = 0; n < 8; n++)
#pragma unroll
            for (int q = 0; q < 4; q++) sf[n][q] = 0.f;

#pragma unroll 4
        for (int kc = 0; kc < 16; kc++) {
            uint32_t af[4];
            const uint32_t* qrow = Qs + (w * 16) * AQ_STR + kc * 8;
            af[0] = qrow[g * AQ_STR + t4];
            af[1] = qrow[(g + 8) * AQ_STR + t4];
            af[2] = qrow[g * AQ_STR + t4 + 4];
            af[3] = qrow[(g + 8) * AQ_STR + t4 + 4];
#pragma unroll
            for (int n = 0; n < 8; n++) {
                uint32_t bf[2];
                const uint32_t* krow = Ks + (n * 8 + g) * KV_STR + kc * 8;
                bf[0] = krow[t4];
                bf[1] = krow[t4 + 4];
                mma_tf32(sf[n], af, bf);
            }
        }

        if (j * 64 + 63 <= q0 + w * 16) {
#pragma unroll
            for (int n = 0; n < 8; n++)
#pragma unroll
                for (int q = 0; q < 4; q++) sf[n][q] *= SCALE;
        } else {
#pragma unroll
            for (int n = 0; n < 8; n++) {
                const int col = j * 64 + n * 8 + 2 * t4;
                sf[n][0] = (col     <= row_lo) ? sf[n][0] * SCALE : -1e30f;
                sf[n][1] = (col + 1 <= row_lo) ? sf[n][1] * SCALE : -1e30f;
                sf[n][2] = (col     <= row_hi) ? sf[n][2] * SCALE : -1e30f;
                sf[n][3] = (col + 1 <= row_hi) ? sf[n][3] * SCALE : -1e30f;
            }
        }

        float tl = -1e30f, th = -1e30f;
#pragma unroll
        for (int n = 0; n < 8; n++) {
            tl = fmaxf(tl, fmaxf(sf[n][0], sf[n][1]));
            th = fmaxf(th, fmaxf(sf[n][2], sf[n][3]));
        }
        tl = fmaxf(tl, __shfl_xor_sync(0xffffffffu, tl, 1));
        tl = fmaxf(tl, __shfl_xor_sync(0xffffffffu, tl, 2));
        th = fmaxf(th, __shfl_xor_sync(0xffffffffu, th, 1));
        th = fmaxf(th, __shfl_xor_sync(0xffffffffu, th, 2));
        const float mn_lo = fmaxf(m_lo, tl);
        const float mn_hi = fmaxf(m_hi, th);
        const float corr_lo = __expf(m_lo - mn_lo);
        const float corr_hi = __expf(m_hi - mn_hi);
        m_lo = mn_lo; m_hi = mn_hi;

        float sum_lo = 0.f, sum_hi = 0.f;
#pragma unroll
        for (int n = 0; n < 8; n++) {
            float p0 = __expf(sf[n][0] - m_lo);
            float p1 = __expf(sf[n][1] - m_lo);
            float p2 = __expf(sf[n][2] - m_hi);
            float p3 = __expf(sf[n][3] - m_hi);
            sum_lo += p0 + p1;
            sum_hi += p2 + p3;
            const int pc = n * 8 + 2 * t4;
            Pw[g * P_STR + pc]           = f2tf32(p0);
            Pw[g * P_STR + pc + 1]       = f2tf32(p1);
            Pw[(g + 8) * P_STR + pc]     = f2tf32(p2);
            Pw[(g + 8) * P_STR + pc + 1] = f2tf32(p3);
        }
        sum_lo += __shfl_xor_sync(0xffffffffu, sum_lo, 1);
        sum_lo += __shfl_xor_sync(0xffffffffu, sum_lo, 2);
        sum_hi += __shfl_xor_sync(0xffffffffu, sum_hi, 1);
        sum_hi += __shfl_xor_sync(0xffffffffu, sum_hi, 2);
        l_lo = l_lo * corr_lo + sum_lo;
        l_hi = l_hi * corr_hi + sum_hi;
#pragma unroll
        for (int dt = 0; dt < 16; dt++) {
            oacc[dt][0] *= corr_lo; oacc[dt][1] *= corr_lo;
            oacc[dt][2] *= corr_hi; oacc[dt][3] *= corr_hi;
        }
        __syncwarp();

        uint32_t paf[8][4];
#pragma unroll
        for (int kc = 0; kc < 8; kc++) {
            paf[kc][0] = Pw[g * P_STR + kc * 8 + t4];
            paf[kc][1] = Pw[(g + 8) * P_STR + kc * 8 + t4];
            paf[kc][2] = Pw[g * P_STR + kc * 8 + t4 + 4];
            paf[kc][3] = Pw[(g + 8) * P_STR + kc * 8 + t4 + 4];
        }
#pragma unroll 2
        for (int dt = 0; dt < 16; dt++) {
#pragma unroll
            for (int kc = 0; kc < 8; kc++) {
                uint32_t bf[2];
                bf[0] = Vs[(kc * 8 + t4) * KV_STR + dt * 8 + g];
                bf[1] = Vs[(kc * 8 + t4 + 4) * KV_STR + dt * 8 + g];
                mma_tf32(oacc[dt], paf[kc], bf);
            }
        }
    }

    const float il_lo = 1.f / l_lo;
    const float il_hi = 1.f / l_hi;
    const int b = bh >> 4, h = bh & 15;
    float* o_lo = Og + ((long)(b * Tp + row_lo)) * Cp + h * Dp;
    float* o_hi = Og + ((long)(b * Tp + row_hi)) * Cp + h * Dp;
#pragma unroll
    for (int dt = 0; dt < 16; dt++) {
        const int col = dt * 8 + 2 * t4;
        float2 v0 = make_float2(__uint_as_float(f2tf32(oacc[dt][0] * il_lo)),
                                __uint_as_float(f2tf32(oacc[dt][1] * il_lo)));
        float2 v1 = make_float2(__uint_as_float(f2tf32(oacc[dt][2] * il_hi)),
                                __uint_as_float(f2tf32(oacc[dt][3] * il_hi)));
        *(float2*)(o_lo + col) = v0;
        *(float2*)(o_hi + col) = v1;
    }
}

// ---------------------------------------------------------------------------
extern "C" void kernel_launch(void* const* d_in, const int* in_sizes, int n_in,
                              void* d_out, int out_size)
{
    const float* x      = (const float*)d_in[0];  // [B,T,C]
    const float* W_attn = (const float*)d_in[1];  // [3C,C]
    const float* W_proj = (const float*)d_in[2];  // [C,C]
    float* out = (float*)d_out;                   // [B,T,C]

    float *pq, *pk, *pv, *pao, *pxc, *pwa, *pwp;
    cudaGetSymbolAddress((void**)&pq,  g_q);
    cudaGetSymbolAddress((void**)&pk,  g_k);
    cudaGetSymbolAddress((void**)&pv,  g_v);
    cudaGetSymbolAddress((void**)&pao, g_ao);
    cudaGetSymbolAddress((void**)&pxc, g_xc);
    cudaGetSymbolAddress((void**)&pwa, g_wa);
    cudaGetSymbolAddress((void**)&pwp, g_wp);

    cudaFuncSetAttribute(attn_tc,
                         cudaFuncAttributeMaxDynamicSharedMemorySize, ATTN2_SMEM);

    // 0) tf32 rounding pre-pass
    {
        int n4x = BTp * Cp / 4, n4a = 3 * Cp * Cp / 4, n4p = Cp * Cp / 4;
        cvt_tf32_kernel<<<(n4x + 255) / 256, 256>>>((const float4*)x,      (float4*)pxc, n4x);
        cvt_tf32_kernel<<<(n4a + 255) / 256, 256>>>((const float4*)W_attn, (float4*)pwa, n4a);
        cvt_tf32_kernel<<<(n4p + 255) / 256, 256>>>((const float4*)W_proj, (float4*)pwp, n4p);
    }
    // 1) QKV projection with scatter into [B,H,T,d]
    {
        dim3 grid(3 * Cp / BN, BTp / BM);
        gemm_mma<1><<<grid, 128>>>(pxc, pwa, pq, pk, pv, BTp, 3 * Cp, Cp);
    }
    // 2) tensor-core causal flash attention -> g_ao [B,T,C] (tf32-rounded)
    {
        dim3 grid(Tp / 128, BHp);
        attn_tc<<<grid, 256, ATTN2_SMEM>>>(pq, pk, pv, pao);
    }
    // 3) output projection
    {
        dim3 grid(Cp / BN, BTp / BM);
        gemm_mma<0><<<grid, 128>>>(pao, pwp, out, nullptr, nullptr, BTp, Cp, Cp);
    }
}